// round 9
// baseline (speedup 1.0000x reference)
#include <cuda_runtime.h>
#include <cuda_bf16.h>
#include <cuda_fp16.h>
#include <stdint.h>

// Problem constants
#define DIMN      1024
#define NUM_HEADS 16
#define HEAD_DIM  64
#define BATCH     2
#define SEQ       2048
#define MROWS     (BATCH * SEQ)          // 4096
#define NELEM     (MROWS * DIMN)         // 4,194,304
#define WELEM     (DIMN * DIMN)          // 1,048,576
#define QK_SCALE  0.125f

// ---------------- scratch (static device globals; no allocation) -----------
__device__ __nv_bfloat16 g_xh[3 * NELEM];   // split hi of q,k,v inputs
__device__ __nv_bfloat16 g_xl[3 * NELEM];   // split lo
__device__ __nv_bfloat16 g_wh[4 * WELEM];   // split hi of Wq,Wk,Wv,Wo
__device__ __nv_bfloat16 g_wl[4 * WELEM];
__device__ __half        g_q16[NELEM];      // fp16 [B,H,L,hd], pre-scaled
__device__ __half        g_k16[NELEM];
__device__ __half        g_v16[NELEM];
__device__ __nv_bfloat16 g_ah[NELEM];       // attn output split hi [B,L,D]
__device__ __nv_bfloat16 g_al[NELEM];       // attn output split lo

// ---------------------------------------------------------------------------
// PTX helpers
// ---------------------------------------------------------------------------
__device__ __forceinline__ uint32_t smem_cast(const void* p) {
    return (uint32_t)__cvta_generic_to_shared(p);
}
__device__ __forceinline__ void cp16(uint32_t s, const void* g) {
    asm volatile("cp.async.cg.shared.global [%0], [%1], 16;" :: "r"(s), "l"(g));
}
__device__ __forceinline__ void cp_commit() {
    asm volatile("cp.async.commit_group;");
}
template <int N>
__device__ __forceinline__ void cp_wait() {
    asm volatile("cp.async.wait_group %0;" :: "n"(N));
}
__device__ __forceinline__ void ldsm4(uint32_t& d0, uint32_t& d1, uint32_t& d2,
                                      uint32_t& d3, uint32_t a) {
    asm volatile("ldmatrix.sync.aligned.m8n8.x4.shared.b16 {%0,%1,%2,%3},[%4];"
                 : "=r"(d0), "=r"(d1), "=r"(d2), "=r"(d3) : "r"(a));
}
__device__ __forceinline__ void ldsm4t(uint32_t& d0, uint32_t& d1, uint32_t& d2,
                                       uint32_t& d3, uint32_t a) {
    asm volatile("ldmatrix.sync.aligned.m8n8.x4.trans.shared.b16 {%0,%1,%2,%3},[%4];"
                 : "=r"(d0), "=r"(d1), "=r"(d2), "=r"(d3) : "r"(a));
}
__device__ __forceinline__ void mma_bf16(float* c, const uint32_t* a,
                                         uint32_t b0, uint32_t b1) {
    asm volatile(
        "mma.sync.aligned.m16n8k16.row.col.f32.bf16.bf16.f32 "
        "{%0,%1,%2,%3},{%4,%5,%6,%7},{%8,%9},{%0,%1,%2,%3};"
        : "+f"(c[0]), "+f"(c[1]), "+f"(c[2]), "+f"(c[3])
        : "r"(a[0]), "r"(a[1]), "r"(a[2]), "r"(a[3]), "r"(b0), "r"(b1));
}
__device__ __forceinline__ void mma_f16(float* c, const uint32_t* a,
                                        uint32_t b0, uint32_t b1) {
    asm volatile(
        "mma.sync.aligned.m16n8k16.row.col.f32.f16.f16.f32 "
        "{%0,%1,%2,%3},{%4,%5,%6,%7},{%8,%9},{%0,%1,%2,%3};"
        : "+f"(c[0]), "+f"(c[1]), "+f"(c[2]), "+f"(c[3])
        : "r"(a[0]), "r"(a[1]), "r"(a[2]), "r"(a[3]), "r"(b0), "r"(b1));
}
__device__ __forceinline__ void split2(float x, float y,
                                       __nv_bfloat162& hi, __nv_bfloat162& lo) {
    __nv_bfloat16 hx = __float2bfloat16(x);
    __nv_bfloat16 hy = __float2bfloat16(y);
    hi.x = hx; hi.y = hy;
    lo.x = __float2bfloat16(x - __bfloat162float(hx));
    lo.y = __float2bfloat16(y - __bfloat162float(hy));
}

// ---------------------------------------------------------------------------
// Split kernel: fp32 -> bf16 hi/lo, up to 4 tensors selected by blockIdx.y.
// ---------------------------------------------------------------------------
__global__ __launch_bounds__(256)
void split_kernel(const float* __restrict__ S0, const float* __restrict__ S1,
                  const float* __restrict__ S2, const float* __restrict__ S3,
                  __nv_bfloat16* __restrict__ H, __nv_bfloat16* __restrict__ L,
                  int n_per)
{
    const int t = blockIdx.y;
    const float* S = (t == 0) ? S0 : (t == 1) ? S1 : (t == 2) ? S2 : S3;
    const int i = (blockIdx.x * 256 + threadIdx.x) * 4;
    if (i >= n_per) return;
    const size_t base = (size_t)t * n_per + i;
    float4 v = *(const float4*)(S + i);
    __nv_bfloat162 h0, l0, h1, l1;
    split2(v.x, v.y, h0, l0);
    split2(v.z, v.w, h1, l1);
    uint2 hp, lp;
    hp.x = *(uint32_t*)&h0; hp.y = *(uint32_t*)&h1;
    lp.x = *(uint32_t*)&l0; lp.y = *(uint32_t*)&l1;
    *(uint2*)(H + base) = hp;
    *(uint2*)(L + base) = lp;
}

// ---------------------------------------------------------------------------
// Split-bf16 tensor-core GEMM v2: CTA tile 256x128, 512 threads (16 warps as
// 8m x 2n, warp tile 32x64), BK=32, 3-stage cp.async pipeline, 180KB smem.
// C = (Ah+Al)[M,K] @ (Wh+Wl)[N,K]^T + bias   (drop Al@Wl)
// mode 0: C fp16 head-split [B,H,L,hd], scaled.  mode 1: C fp32 flat [M,N].
// ---------------------------------------------------------------------------
#define GSTR      40                       // smem row stride in bf16 (80B)
#define G_A_ELE   (256 * GSTR)             // 10240
#define G_B_ELE   (128 * GSTR)             // 5120
#define G_STAGE_E (2 * G_A_ELE + 2 * G_B_ELE)
#define G_STAGE_B (G_STAGE_E * 2)          // 61440 bytes
#define G_STAGES  3
#define G_SMEM    (G_STAGES * G_STAGE_B)   // 184320 bytes

__global__ __launch_bounds__(512, 1)
void gemm_ts_kernel(const __nv_bfloat16* __restrict__ Ah,
                    const __nv_bfloat16* __restrict__ Al,
                    const __nv_bfloat16* __restrict__ Wh,
                    const __nv_bfloat16* __restrict__ Wl,
                    const float* __restrict__ bias,
                    __half* __restrict__ Ch, float* __restrict__ Cf,
                    float scale, int mode)
{
    extern __shared__ __nv_bfloat16 sg[];
    const int tid  = threadIdx.x;
    const int lane = tid & 31;
    const int wid  = tid >> 5;
    const int wm   = wid & 7;        // 8 m-warps x 32 rows
    const int wn   = wid >> 3;       // 2 n-warps x 64 cols
    const int m0   = blockIdx.y * 256;
    const int n0   = blockIdx.x * 128;

    const uint32_t sbase = smem_cast(sg);

    // cp.async mapping: chunk c -> row c>>2, col (c&3)*8 (rows of 32 bf16)
    const int crow = tid >> 2;            // 0..127
    const int ccol = (tid & 3) << 3;      // 0,8,16,24
    const __nv_bfloat16* gAh0 = Ah + (size_t)(m0 + crow) * DIMN + ccol;
    const __nv_bfloat16* gAh1 = gAh0 + (size_t)128 * DIMN;
    const __nv_bfloat16* gAl0 = Al + (size_t)(m0 + crow) * DIMN + ccol;
    const __nv_bfloat16* gAl1 = gAl0 + (size_t)128 * DIMN;
    const __nv_bfloat16* gWh0 = Wh + (size_t)(n0 + crow) * DIMN + ccol;
    const __nv_bfloat16* gWl0 = Wl + (size_t)(n0 + crow) * DIMN + ccol;
    const uint32_t so0 = (uint32_t)(crow * GSTR + ccol) * 2;           // rows 0..127
    const uint32_t so1 = so0 + (uint32_t)(128 * GSTR) * 2;             // rows 128..255

    float acc[2][8][4];
#pragma unroll
    for (int i = 0; i < 2; ++i)
#pragma unroll
        for (int j = 0; j < 8; ++j)
#pragma unroll
            for (int q = 0; q < 4; ++q) acc[i][j][q] = 0.0f;

    // ldmatrix offsets (bytes, within one matrix region)
    const int arow = wm * 32 + (lane & 15);
    const uint32_t aoff0 = (uint32_t)(arow * GSTR + (lane >> 4) * 8) * 2;
    const uint32_t aoff1 = aoff0 + (uint32_t)(16 * GSTR) * 2;
    const int bn = wn * 64 + ((lane >> 4) << 3) + (lane & 7);
    const uint32_t boff = (uint32_t)(bn * GSTR + ((lane >> 3) & 1) * 8) * 2;

#define G_ISSUE(KT, ST)                                                       \
    do {                                                                      \
        uint32_t sb_ = sbase + (uint32_t)(ST) * G_STAGE_B;                    \
        cp16(sb_ + so0, gAh0 + (KT));                                         \
        cp16(sb_ + so1, gAh1 + (KT));                                         \
        cp16(sb_ + G_A_ELE * 2 + so0, gAl0 + (KT));                           \
        cp16(sb_ + G_A_ELE * 2 + so1, gAl1 + (KT));                           \
        cp16(sb_ + 2 * G_A_ELE * 2 + so0, gWh0 + (KT));                       \
        cp16(sb_ + 2 * G_A_ELE * 2 + G_B_ELE * 2 + so0, gWl0 + (KT));         \
    } while (0)

    // prologue: stages 0,1
    G_ISSUE(0, 0);  cp_commit();
    G_ISSUE(32, 1); cp_commit();

    const int NKT = DIMN / 32;   // 32
    for (int kt = 0; kt < NKT; ++kt) {
        cp_wait<1>();
        __syncthreads();
        if (kt + 2 < NKT) G_ISSUE((kt + 2) * 32, (kt + 2) % 3);
        cp_commit();

        const uint32_t sb  = sbase + (uint32_t)(kt % 3) * G_STAGE_B;
        const uint32_t aAh = sb;
        const uint32_t aAl = sb + G_A_ELE * 2;
        const uint32_t aBh = sb + 2 * G_A_ELE * 2;
        const uint32_t aBl = aBh + G_B_ELE * 2;

#pragma unroll
        for (int ks = 0; ks < 2; ++ks) {
            const uint32_t ko = (uint32_t)ks * 32;   // 16 bf16 = 32 bytes
            uint32_t ah0[4], ah1[4], al0[4], al1[4];
            ldsm4(ah0[0], ah0[1], ah0[2], ah0[3], aAh + aoff0 + ko);
            ldsm4(ah1[0], ah1[1], ah1[2], ah1[3], aAh + aoff1 + ko);
            ldsm4(al0[0], al0[1], al0[2], al0[3], aAl + aoff0 + ko);
            ldsm4(al1[0], al1[1], al1[2], al1[3], aAl + aoff1 + ko);
#pragma unroll
            for (int p = 0; p < 4; ++p) {
                uint32_t bh[4], bl[4];
                const uint32_t po = (uint32_t)(p * 16 * GSTR) * 2 + ko;
                ldsm4(bh[0], bh[1], bh[2], bh[3], aBh + boff + po);
                ldsm4(bl[0], bl[1], bl[2], bl[3], aBl + boff + po);
                // hh group (acc reuse distance 4)
                mma_bf16(acc[0][2 * p],     ah0, bh[0], bh[1]);
                mma_bf16(acc[1][2 * p],     ah1, bh[0], bh[1]);
                mma_bf16(acc[0][2 * p + 1], ah0, bh[2], bh[3]);
                mma_bf16(acc[1][2 * p + 1], ah1, bh[2], bh[3]);
                // hl group
                mma_bf16(acc[0][2 * p],     ah0, bl[0], bl[1]);
                mma_bf16(acc[1][2 * p],     ah1, bl[0], bl[1]);
                mma_bf16(acc[0][2 * p + 1], ah0, bl[2], bl[3]);
                mma_bf16(acc[1][2 * p + 1], ah1, bl[2], bl[3]);
                // lh group
                mma_bf16(acc[0][2 * p],     al0, bh[0], bh[1]);
                mma_bf16(acc[1][2 * p],     al1, bh[0], bh[1]);
                mma_bf16(acc[0][2 * p + 1], al0, bh[2], bh[3]);
                mma_bf16(acc[1][2 * p + 1], al1, bh[2], bh[3]);
            }
        }
    }
#undef G_ISSUE

    // epilogue
#pragma unroll
    for (int mt = 0; mt < 2; ++mt) {
#pragma unroll
        for (int nt = 0; nt < 8; ++nt) {
            const int rr = m0 + wm * 32 + mt * 16 + (lane >> 2);
            const int cc = n0 + wn * 64 + nt * 8 + ((lane & 3) << 1);
            const float2 bv = *(const float2*)&bias[cc];
            const float o00 = acc[mt][nt][0] + bv.x;
            const float o01 = acc[mt][nt][1] + bv.y;
            const float o10 = acc[mt][nt][2] + bv.x;
            const float o11 = acc[mt][nt][3] + bv.y;
            if (mode == 1) {
                float2 a = {o00, o01}, b = {o10, o11};
                *(float2*)&Cf[(size_t)rr * DIMN + cc]       = a;
                *(float2*)&Cf[(size_t)(rr + 8) * DIMN + cc] = b;
            } else {
                const int h = cc >> 6, hd = cc & 63;
                {
                    const int b = rr >> 11, l = rr & 2047;
                    size_t d = ((((size_t)b * NUM_HEADS + h) * SEQ + l) * HEAD_DIM + hd);
                    *(__half2*)&Ch[d] = __floats2half2_rn(o00 * scale, o01 * scale);
                }
                {
                    const int r2 = rr + 8;
                    const int b = r2 >> 11, l = r2 & 2047;
                    size_t d = ((((size_t)b * NUM_HEADS + h) * SEQ + l) * HEAD_DIM + hd);
                    *(__half2*)&Ch[d] = __floats2half2_rn(o10 * scale, o11 * scale);
                }
            }
        }
    }
}

// ---------------------------------------------------------------------------
// Tensor-core flash attention v2: 128 threads (4 warps), 32 queries/warp
// (two m16 q-tiles SHARING every K/V ldmatrix fragment -> half the smem
// traffic per query). fp16 MMA, fp32 accum, 3-stage cp.async.
// Output: split bf16 hi/lo [B,L,D].
// ---------------------------------------------------------------------------
#define ASTR     72
#define A_STAGES 3

struct AttnStage {
    __half Ks[64 * ASTR];
    __half Vs[64 * ASTR];
    int    Ms[64];
};
#define A_SMEM (A_STAGES * (int)sizeof(AttnStage))

__global__ __launch_bounds__(128, 2)
void attn_mma_kernel(const __half* __restrict__ Qh, const __half* __restrict__ Kh,
                     const __half* __restrict__ Vh, const int* __restrict__ kv_mask,
                     __nv_bfloat16* __restrict__ OutH,
                     __nv_bfloat16* __restrict__ OutL)
{
    extern __shared__ char asm_raw[];
    AttnStage* stg = (AttnStage*)asm_raw;

    const int tid  = threadIdx.x;
    const int lane = tid & 31;
    const int wid  = tid >> 5;
    const int bh   = blockIdx.y;
    const int b    = bh >> 4;
    const int h    = bh & 15;
    const int q0   = blockIdx.x * 128 + wid * 32;   // warp's first query (32 q/warp)

    const __half* Kb = Kh + (size_t)bh * SEQ * HEAD_DIM;
    const __half* Vb = Vh + (size_t)bh * SEQ * HEAD_DIM;
    const int*    Mb = kv_mask + b * SEQ;

#define A_ISSUE(J0, ST)                                                        \
    do {                                                                       \
        uint32_t sK_ = smem_cast(stg[ST].Ks);                                  \
        uint32_t sV_ = smem_cast(stg[ST].Vs);                                  \
        uint32_t sM_ = smem_cast(stg[ST].Ms);                                  \
        for (int idx = tid; idx < 1040; idx += 128) {                          \
            if (idx < 512) {                                                   \
                int rr = idx >> 3, cc = idx & 7;                               \
                cp16(sK_ + (uint32_t)(rr * ASTR + cc * 8) * 2,                 \
                     Kb + (size_t)((J0) + rr) * HEAD_DIM + cc * 8);            \
            } else if (idx < 1024) {                                           \
                int q = idx - 512, rr = q >> 3, cc = q & 7;                    \
                cp16(sV_ + (uint32_t)(rr * ASTR + cc * 8) * 2,                 \
                     Vb + (size_t)((J0) + rr) * HEAD_DIM + cc * 8);            \
            } else {                                                           \
                int q = idx - 1024;                                            \
                cp16(sM_ + (uint32_t)q * 16, Mb + (J0) + q * 4);               \
            }                                                                  \
        }                                                                      \
    } while (0)

    // prologue: stages 0,1
    A_ISSUE(0, 0);  cp_commit();
    A_ISSUE(64, 1); cp_commit();

    // Q fragments for both q-tiles (already scaled fp16)
    uint32_t aq[2][4][4];
    {
        const __half* Qb = Qh + (size_t)bh * SEQ * HEAD_DIM;
#pragma unroll
        for (int qt = 0; qt < 2; ++qt)
#pragma unroll
            for (int ks = 0; ks < 4; ++ks)
#pragma unroll
                for (int j = 0; j < 4; ++j) {
                    const int rr = q0 + qt * 16 + (lane >> 2) + (j & 1) * 8;
                    const int cc = ks * 16 + ((j >> 1) << 3) + ((lane & 3) << 1);
                    aq[qt][ks][j] = *(const uint32_t*)&Qb[(size_t)rr * HEAD_DIM + cc];
                }
    }

    float O[2][8][4];
#pragma unroll
    for (int qt = 0; qt < 2; ++qt)
#pragma unroll
        for (int i = 0; i < 8; ++i)
#pragma unroll
            for (int j = 0; j < 4; ++j) O[qt][i][j] = 0.0f;
    float mr[2][2] = {{-1e30f, -1e30f}, {-1e30f, -1e30f}};
    float lr[2][2] = {{0.0f, 0.0f}, {0.0f, 0.0f}};

    const uint32_t kfrag =
        (uint32_t)(((((lane >> 4) << 3) + (lane & 7)) * ASTR + ((lane >> 3) & 1) * 8)) * 2;
    const uint32_t vfrag =
        (uint32_t)((((((lane >> 3) & 1) << 3) + (lane & 7)) * ASTR + (lane >> 4) * 8)) * 2;

    const int NT = SEQ / 64;   // 32
    for (int kt = 0; kt < NT; ++kt) {
        cp_wait<1>();
        __syncthreads();
        if (kt + 2 < NT) A_ISSUE((kt + 2) * 64, (kt + 2) % A_STAGES);
        cp_commit();

        AttnStage* st = &stg[kt % A_STAGES];
        const uint32_t aK = smem_cast(st->Ks);
        const uint32_t aV = smem_cast(st->Vs);

        // ---- S = Q @ K^T (both q-tiles share each K fragment) ----
        float S[2][8][4];
#pragma unroll
        for (int qt = 0; qt < 2; ++qt)
#pragma unroll
            for (int i = 0; i < 8; ++i)
#pragma unroll
                for (int j = 0; j < 4; ++j) S[qt][i][j] = 0.0f;
#pragma unroll
        for (int ks = 0; ks < 4; ++ks) {
#pragma unroll
            for (int p = 0; p < 4; ++p) {
                uint32_t bq[4];
                ldsm4(bq[0], bq[1], bq[2], bq[3],
                      aK + kfrag + (uint32_t)(p * 16 * ASTR * 2 + ks * 32));
                mma_f16(S[0][2 * p],     aq[0][ks], bq[0], bq[1]);
                mma_f16(S[1][2 * p],     aq[1][ks], bq[0], bq[1]);
                mma_f16(S[0][2 * p + 1], aq[0][ks], bq[2], bq[3]);
                mma_f16(S[1][2 * p + 1], aq[1][ks], bq[2], bq[3]);
            }
        }

        // ---- mask + online softmax per q-tile ----
        float fct[2][2];
#pragma unroll
        for (int qt = 0; qt < 2; ++qt) {
            float mx0 = -1e30f, mx1 = -1e30f;
#pragma unroll
            for (int nt = 0; nt < 8; ++nt) {
                const int kk = nt * 8 + ((lane & 3) << 1);
                const int2 mi = *(const int2*)&st->Ms[kk];
                const float mdx = mi.x ? 0.0f : -1e30f;
                const float mdy = mi.y ? 0.0f : -1e30f;
                S[qt][nt][0] += mdx; S[qt][nt][1] += mdy;
                S[qt][nt][2] += mdx; S[qt][nt][3] += mdy;
                mx0 = fmaxf(mx0, fmaxf(S[qt][nt][0], S[qt][nt][1]));
                mx1 = fmaxf(mx1, fmaxf(S[qt][nt][2], S[qt][nt][3]));
            }
            mx0 = fmaxf(mx0, __shfl_xor_sync(0xffffffffu, mx0, 1));
            mx0 = fmaxf(mx0, __shfl_xor_sync(0xffffffffu, mx0, 2));
            mx1 = fmaxf(mx1, __shfl_xor_sync(0xffffffffu, mx1, 1));
            mx1 = fmaxf(mx1, __shfl_xor_sync(0xffffffffu, mx1, 2));

            const float nm0 = fmaxf(mr[qt][0], mx0), nm1 = fmaxf(mr[qt][1], mx1);
            fct[qt][0] = __expf(mr[qt][0] - nm0);
            fct[qt][1] = __expf(mr[qt][1] - nm1);
            mr[qt][0] = nm0; mr[qt][1] = nm1;

            float s0 = 0.0f, s1 = 0.0f;
#pragma unroll
            for (int nt = 0; nt < 8; ++nt) {
                S[qt][nt][0] = __expf(S[qt][nt][0] - nm0);
                S[qt][nt][1] = __expf(S[qt][nt][1] - nm0);
                S[qt][nt][2] = __expf(S[qt][nt][2] - nm1);
                S[qt][nt][3] = __expf(S[qt][nt][3] - nm1);
                s0 += S[qt][nt][0] + S[qt][nt][1];
                s1 += S[qt][nt][2] + S[qt][nt][3];
            }
            s0 += __shfl_xor_sync(0xffffffffu, s0, 1);
            s0 += __shfl_xor_sync(0xffffffffu, s0, 2);
            s1 += __shfl_xor_sync(0xffffffffu, s1, 1);
            s1 += __shfl_xor_sync(0xffffffffu, s1, 2);
            lr[qt][0] = lr[qt][0] * fct[qt][0] + s0;
            lr[qt][1] = lr[qt][1] * fct[qt][1] + s1;

#pragma unroll
            for (int nt = 0; nt < 8; ++nt) {
                O[qt][nt][0] *= fct[qt][0]; O[qt][nt][1] *= fct[qt][0];
                O[qt][nt][2] *= fct[qt][1]; O[qt][nt][3] *= fct[qt][1];
            }
        }

        // ---- O += P @ V (both q-tiles share each V fragment) ----
#pragma unroll
        for (int ks = 0; ks < 4; ++ks) {
            uint32_t pa0[4], pa1[4];
            {
                __half2 t0 = __floats2half2_rn(S[0][2 * ks][0],     S[0][2 * ks][1]);
                __half2 t1 = __floats2half2_rn(S[0][2 * ks][2],     S[0][2 * ks][3]);
                __half2 t2 = __floats2half2_rn(S[0][2 * ks + 1][0], S[0][2 * ks + 1][1]);
                __half2 t3 = __floats2half2_rn(S[0][2 * ks + 1][2], S[0][2 * ks + 1][3]);
                pa0[0] = *(uint32_t*)&t0; pa0[1] = *(uint32_t*)&t1;
                pa0[2] = *(uint32_t*)&t2; pa0[3] = *(uint32_t*)&t3;
                __half2 u0 = __floats2half2_rn(S[1][2 * ks][0],     S[1][2 * ks][1]);
                __half2 u1 = __floats2half2_rn(S[1][2 * ks][2],     S[1][2 * ks][3]);
                __half2 u2 = __floats2half2_rn(S[1][2 * ks + 1][0], S[1][2 * ks + 1][1]);
                __half2 u3 = __floats2half2_rn(S[1][2 * ks + 1][2], S[1][2 * ks + 1][3]);
                pa1[0] = *(uint32_t*)&u0; pa1[1] = *(uint32_t*)&u1;
                pa1[2] = *(uint32_t*)&u2; pa1[3] = *(uint32_t*)&u3;
            }
#pragma unroll
            for (int p = 0; p < 4; ++p) {
                uint32_t bv[4];
                ldsm4t(bv[0], bv[1], bv[2], bv[3],
                       aV + vfrag + (uint32_t)(ks * 16 * ASTR * 2 + p * 32));
                mma_f16(O[0][2 * p],     pa0, bv[0], bv[1]);
                mma_f16(O[1][2 * p],     pa1, bv[0], bv[1]);
                mma_f16(O[0][2 * p + 1], pa0, bv[2], bv[3]);
                mma_f16(O[1][2 * p + 1], pa1, bv[2], bv[3]);
            }
        }
    }
#undef A_ISSUE

    // ---- normalize + split-bf16 store to [B,L,D] ----
#pragma unroll
    for (int qt = 0; qt < 2; ++qt) {
        const float inv0 = 1.0f / lr[qt][0], inv1 = 1.0f / lr[qt][1];
        const int qr = q0 + qt * 16 + (lane >> 2);
        const size_t base0 = ((size_t)b * SEQ + qr) * DIMN + h * HEAD_DIM;
        const size_t base1 = ((size_t)b * SEQ + qr + 8) * DIMN + h * HEAD_DIM;
#pragma unroll
        for (int nt = 0; nt < 8; ++nt) {
            const int c = nt * 8 + ((lane & 3) << 1);
            __nv_bfloat162 h0, l0, h1, l1;
            split2(O[qt][nt][0] * inv0, O[qt][nt][1] * inv0, h0, l0);
            split2(O[qt][nt][2] * inv1, O[qt][nt][3] * inv1, h1, l1);
            *(__nv_bfloat162*)&OutH[base0 + c] = h0;
            *(__nv_bfloat162*)&OutL[base0 + c] = l0;
            *(__nv_bfloat162*)&OutH[base1 + c] = h1;
            *(__nv_bfloat162*)&OutL[base1 + c] = l1;
        }
    }
}

// ---------------------------------------------------------------------------
extern "C" void kernel_launch(void* const* d_in, const int* in_sizes, int n_in,
                              void* d_out, int out_size)
{
    const float* q    = (const float*)d_in[0];
    const float* k    = (const float*)d_in[1];
    const float* v    = (const float*)d_in[2];
    const int*   mask = (const int*)  d_in[3];
    const float* Wq   = (const float*)d_in[4];
    const float* bq   = (const float*)d_in[5];
    const float* Wk   = (const float*)d_in[6];
    const float* bk   = (const float*)d_in[7];
    const float* Wv   = (const float*)d_in[8];
    const float* bv   = (const float*)d_in[9];
    const float* Wo   = (const float*)d_in[10];
    const float* bo   = (const float*)d_in[11];
    float*       out  = (float*)d_out;

    static bool attr_done = false;
    if (!attr_done) {
        cudaFuncSetAttribute(gemm_ts_kernel,
                             cudaFuncAttributeMaxDynamicSharedMemorySize, G_SMEM);
        cudaFuncSetAttribute(attn_mma_kernel,
                             cudaFuncAttributeMaxDynamicSharedMemorySize, A_SMEM);
        attr_done = true;
    }

    void *p_xh, *p_xl, *p_wh, *p_wl, *p_q16, *p_k16, *p_v16, *p_ah, *p_al;
    cudaGetSymbolAddress(&p_xh,  g_xh);
    cudaGetSymbolAddress(&p_xl,  g_xl);
    cudaGetSymbolAddress(&p_wh,  g_wh);
    cudaGetSymbolAddress(&p_wl,  g_wl);
    cudaGetSymbolAddress(&p_q16, g_q16);
    cudaGetSymbolAddress(&p_k16, g_k16);
    cudaGetSymbolAddress(&p_v16, g_v16);
    cudaGetSymbolAddress(&p_ah,  g_ah);
    cudaGetSymbolAddress(&p_al,  g_al);

    __nv_bfloat16* xh = (__nv_bfloat16*)p_xh;
    __nv_bfloat16* xl = (__nv_bfloat16*)p_xl;
    __nv_bfloat16* wh = (__nv_bfloat16*)p_wh;
    __nv_bfloat16* wl = (__nv_bfloat16*)p_wl;

    // split inputs (3 x 4M) and weights (4 x 1M)
    split_kernel<<<dim3(NELEM / 1024, 3), 256>>>(q, k, v, nullptr, xh, xl, NELEM);
    split_kernel<<<dim3(WELEM / 1024, 4), 256>>>(Wq, Wk, Wv, Wo, wh, wl, WELEM);

    dim3 gg(DIMN / 128, MROWS / 256);   // (8, 16) = 128 CTAs, one wave
    gemm_ts_kernel<<<gg, 512, G_SMEM>>>(xh, xl, wh, wl, bq,
                                        (__half*)p_q16, nullptr, QK_SCALE, 0);
    gemm_ts_kernel<<<gg, 512, G_SMEM>>>(xh + (size_t)NELEM, xl + (size_t)NELEM,
                                        wh + (size_t)WELEM, wl + (size_t)WELEM, bk,
                                        (__half*)p_k16, nullptr, 1.0f, 0);
    gemm_ts_kernel<<<gg, 512, G_SMEM>>>(xh + 2 * (size_t)NELEM, xl + 2 * (size_t)NELEM,
                                        wh + 2 * (size_t)WELEM, wl + 2 * (size_t)WELEM, bv,
                                        (__half*)p_v16, nullptr, 1.0f, 0);

    dim3 ag(SEQ / 128, BATCH * NUM_HEADS);   // (16, 32)
    attn_mma_kernel<<<ag, 128, A_SMEM>>>((const __half*)p_q16, (const __half*)p_k16,
                                         (const __half*)p_v16, mask,
                                         (__nv_bfloat16*)p_ah, (__nv_bfloat16*)p_al);

    gemm_ts_kernel<<<gg, 512, G_SMEM>>>((__nv_bfloat16*)p_ah, (__nv_bfloat16*)p_al,
                                        wh + 3 * (size_t)WELEM, wl + 3 * (size_t)WELEM, bo,
                                        nullptr, out, 1.0f, 1);
}

// round 14
// speedup vs baseline: 1.4820x; 1.4820x over previous
#include <cuda_runtime.h>
#include <cuda_bf16.h>
#include <cuda_fp16.h>
#include <stdint.h>

// Problem constants
#define DIMN      1024
#define NUM_HEADS 16
#define HEAD_DIM  64
#define BATCH     2
#define SEQ       2048
#define MROWS     (BATCH * SEQ)          // 4096
#define NELEM     (MROWS * DIMN)         // 4,194,304
#define WELEM     (DIMN * DIMN)          // 1,048,576
#define QK_SCALE  0.125f

// ---------------- scratch (static device globals; no allocation) -----------
__device__ __nv_bfloat16 g_xh[3 * NELEM];   // split hi of q,k,v inputs
__device__ __nv_bfloat16 g_xl[3 * NELEM];   // split lo
__device__ __nv_bfloat16 g_wh[4 * WELEM];   // split hi of Wq,Wk,Wv,Wo
__device__ __nv_bfloat16 g_wl[4 * WELEM];
__device__ __half        g_q16[NELEM];      // fp16 [B,H,L,hd], pre-scaled
__device__ __half        g_k16[NELEM];
__device__ __half        g_v16[NELEM];
__device__ __nv_bfloat16 g_ah[NELEM];       // attn output split hi [B,L,D]
__device__ __nv_bfloat16 g_al[NELEM];       // attn output split lo

// ---------------------------------------------------------------------------
// PTX helpers
// ---------------------------------------------------------------------------
__device__ __forceinline__ uint32_t smem_cast(const void* p) {
    return (uint32_t)__cvta_generic_to_shared(p);
}
__device__ __forceinline__ void cp16(uint32_t s, const void* g) {
    asm volatile("cp.async.cg.shared.global [%0], [%1], 16;" :: "r"(s), "l"(g));
}
__device__ __forceinline__ void cp_commit() {
    asm volatile("cp.async.commit_group;");
}
template <int N>
__device__ __forceinline__ void cp_wait() {
    asm volatile("cp.async.wait_group %0;" :: "n"(N));
}
__device__ __forceinline__ void ldsm4(uint32_t& d0, uint32_t& d1, uint32_t& d2,
                                      uint32_t& d3, uint32_t a) {
    asm volatile("ldmatrix.sync.aligned.m8n8.x4.shared.b16 {%0,%1,%2,%3},[%4];"
                 : "=r"(d0), "=r"(d1), "=r"(d2), "=r"(d3) : "r"(a));
}
__device__ __forceinline__ void ldsm4t(uint32_t& d0, uint32_t& d1, uint32_t& d2,
                                       uint32_t& d3, uint32_t a) {
    asm volatile("ldmatrix.sync.aligned.m8n8.x4.trans.shared.b16 {%0,%1,%2,%3},[%4];"
                 : "=r"(d0), "=r"(d1), "=r"(d2), "=r"(d3) : "r"(a));
}
__device__ __forceinline__ void mma_bf16(float* c, const uint32_t* a,
                                         uint32_t b0, uint32_t b1) {
    asm volatile(
        "mma.sync.aligned.m16n8k16.row.col.f32.bf16.bf16.f32 "
        "{%0,%1,%2,%3},{%4,%5,%6,%7},{%8,%9},{%0,%1,%2,%3};"
        : "+f"(c[0]), "+f"(c[1]), "+f"(c[2]), "+f"(c[3])
        : "r"(a[0]), "r"(a[1]), "r"(a[2]), "r"(a[3]), "r"(b0), "r"(b1));
}
__device__ __forceinline__ void mma_f16(float* c, const uint32_t* a,
                                        uint32_t b0, uint32_t b1) {
    asm volatile(
        "mma.sync.aligned.m16n8k16.row.col.f32.f16.f16.f32 "
        "{%0,%1,%2,%3},{%4,%5,%6,%7},{%8,%9},{%0,%1,%2,%3};"
        : "+f"(c[0]), "+f"(c[1]), "+f"(c[2]), "+f"(c[3])
        : "r"(a[0]), "r"(a[1]), "r"(a[2]), "r"(a[3]), "r"(b0), "r"(b1));
}
__device__ __forceinline__ void split2(float x, float y,
                                       __nv_bfloat162& hi, __nv_bfloat162& lo) {
    __nv_bfloat16 hx = __float2bfloat16(x);
    __nv_bfloat16 hy = __float2bfloat16(y);
    hi.x = hx; hi.y = hy;
    lo.x = __float2bfloat16(x - __bfloat162float(hx));
    lo.y = __float2bfloat16(y - __bfloat162float(hy));
}

// ---------------------------------------------------------------------------
// Split kernel: fp32 -> bf16 hi/lo, up to 4 tensors selected by blockIdx.y.
// ---------------------------------------------------------------------------
__global__ __launch_bounds__(256)
void split_kernel(const float* __restrict__ S0, const float* __restrict__ S1,
                  const float* __restrict__ S2, const float* __restrict__ S3,
                  __nv_bfloat16* __restrict__ H, __nv_bfloat16* __restrict__ L,
                  int n_per)
{
    const int t = blockIdx.y;
    const float* S = (t == 0) ? S0 : (t == 1) ? S1 : (t == 2) ? S2 : S3;
    const int i = (blockIdx.x * 256 + threadIdx.x) * 4;
    if (i >= n_per) return;
    const size_t base = (size_t)t * n_per + i;
    float4 v = *(const float4*)(S + i);
    __nv_bfloat162 h0, l0, h1, l1;
    split2(v.x, v.y, h0, l0);
    split2(v.z, v.w, h1, l1);
    uint2 hp, lp;
    hp.x = *(uint32_t*)&h0; hp.y = *(uint32_t*)&h1;
    lp.x = *(uint32_t*)&l0; lp.y = *(uint32_t*)&l1;
    *(uint2*)(H + base) = hp;
    *(uint2*)(L + base) = lp;
}

// ---------------------------------------------------------------------------
// Split-bf16 tensor-core GEMM v3: CTA tile 256x128, 256 threads, 8 warps as
// 4m x 2n with 64x64 warp tiles, BK=32, 3-stage cp.async (180KB smem,
// 1 CTA/SM), grid = 128 CTAs = one clean wave.
// C = (Ah+Al)[M,K] @ (Wh+Wl)[N,K]^T + bias   (drop Al@Wl)
// mode 0: C fp16 head-split [B,H,L,hd], scaled.  mode 1: C fp32 flat [M,N].
// ---------------------------------------------------------------------------
#define GSTR      40                        // smem row stride in bf16 (80B)
#define T_A_ELE   (256 * GSTR)              // 10240 bf16 per A matrix (256x32)
#define T_W_ELE   (128 * GSTR)              // 5120  bf16 per W matrix (128x32)
#define T_STG_E   (2 * T_A_ELE + 2 * T_W_ELE)
#define T_STG_B   (T_STG_E * 2)             // 61440 bytes
#define T_STAGES  3
#define T_SMEM    (T_STAGES * T_STG_B)      // 184320 bytes

__global__ __launch_bounds__(256, 1)
void gemm_ts_kernel(const __nv_bfloat16* __restrict__ Ah,
                    const __nv_bfloat16* __restrict__ Al,
                    const __nv_bfloat16* __restrict__ Wh,
                    const __nv_bfloat16* __restrict__ Wl,
                    const float* __restrict__ bias,
                    __half* __restrict__ Ch, float* __restrict__ Cf,
                    float scale, int mode)
{
    extern __shared__ __nv_bfloat16 sg[];
    const int tid  = threadIdx.x;
    const int lane = tid & 31;
    const int wid  = tid >> 5;
    const int wm   = wid & 3;        // 4 m-warps x 64 rows
    const int wn   = wid >> 2;       // 2 n-warps x 64 cols
    const int m0   = blockIdx.y * 256;
    const int n0   = blockIdx.x * 128;

    const uint32_t sbase = smem_cast(sg);

    // cp.async mapping: idx -> row idx>>2, col (idx&3)*8
    const int ar = tid >> 2;              // 0..63 (+k*64)
    const int ac = (tid & 3) << 3;        // 0,8,16,24

    float acc[4][8][4];
#pragma unroll
    for (int i = 0; i < 4; ++i)
#pragma unroll
        for (int j = 0; j < 8; ++j)
#pragma unroll
            for (int q = 0; q < 4; ++q) acc[i][j][q] = 0.0f;

    // ldmatrix offsets (bytes, within one matrix region)
    const uint32_t aoff = (uint32_t)((wm * 64 + (lane & 15)) * GSTR +
                                     (lane >> 4) * 8) * 2;
    const int bn = wn * 64 + ((lane >> 4) << 3) + (lane & 7);
    const uint32_t boff = (uint32_t)(bn * GSTR + ((lane >> 3) & 1) * 8) * 2;

#define T_LOAD(KT, ST)                                                        \
    do {                                                                      \
        const uint32_t sb_ = sbase + (uint32_t)(ST) * T_STG_B;                \
        const int kc0 = (KT) * 32;                                            \
        _Pragma("unroll")                                                     \
        for (int i = 0; i < 4; ++i) {                                         \
            const int r = ar + i * 64;                                        \
            const uint32_t so = (uint32_t)(r * GSTR + ac) * 2;                \
            const size_t go = (size_t)(m0 + r) * DIMN + kc0 + ac;             \
            cp16(sb_ + so, Ah + go);                                          \
            cp16(sb_ + T_A_ELE * 2 + so, Al + go);                            \
        }                                                                     \
        _Pragma("unroll")                                                     \
        for (int i = 0; i < 2; ++i) {                                         \
            const int r = ar + i * 64;                                        \
            const uint32_t so = (uint32_t)(r * GSTR + ac) * 2;                \
            const size_t go = (size_t)(n0 + r) * DIMN + kc0 + ac;             \
            cp16(sb_ + 2 * T_A_ELE * 2 + so, Wh + go);                        \
            cp16(sb_ + 2 * T_A_ELE * 2 + T_W_ELE * 2 + so, Wl + go);          \
        }                                                                     \
    } while (0)

    // prologue: stages 0,1
    T_LOAD(0, 0); cp_commit();
    T_LOAD(1, 1); cp_commit();

    const int NKT = DIMN / 32;   // 32
    for (int kt = 0; kt < NKT; ++kt) {
        cp_wait<1>();
        __syncthreads();
        if (kt + 2 < NKT) T_LOAD(kt + 2, (kt + 2) % 3);
        cp_commit();

        const uint32_t sb  = sbase + (uint32_t)(kt % 3) * T_STG_B;
        const uint32_t aAh = sb;
        const uint32_t aAl = sb + T_A_ELE * 2;
        const uint32_t aBh = sb + 2 * T_A_ELE * 2;
        const uint32_t aBl = aBh + T_W_ELE * 2;

#pragma unroll
        for (int ks = 0; ks < 2; ++ks) {
            const uint32_t ko = (uint32_t)ks * 32;   // 16 bf16 = 32 bytes
            uint32_t ah[4][4], al[4][4];
#pragma unroll
            for (int mt = 0; mt < 4; ++mt) {
                const uint32_t mo = (uint32_t)(mt * 16 * GSTR) * 2 + ko;
                ldsm4(ah[mt][0], ah[mt][1], ah[mt][2], ah[mt][3], aAh + aoff + mo);
                ldsm4(al[mt][0], al[mt][1], al[mt][2], al[mt][3], aAl + aoff + mo);
            }
#pragma unroll
            for (int p = 0; p < 4; ++p) {
                uint32_t bh[4], bl[4];
                const uint32_t po = (uint32_t)(p * 16 * GSTR) * 2 + ko;
                ldsm4(bh[0], bh[1], bh[2], bh[3], aBh + boff + po);
                ldsm4(bl[0], bl[1], bl[2], bl[3], aBl + boff + po);
                // hh term (acc reuse distance 8)
#pragma unroll
                for (int mt = 0; mt < 4; ++mt) {
                    mma_bf16(acc[mt][2 * p],     ah[mt], bh[0], bh[1]);
                    mma_bf16(acc[mt][2 * p + 1], ah[mt], bh[2], bh[3]);
                }
                // hl term
#pragma unroll
                for (int mt = 0; mt < 4; ++mt) {
                    mma_bf16(acc[mt][2 * p],     ah[mt], bl[0], bl[1]);
                    mma_bf16(acc[mt][2 * p + 1], ah[mt], bl[2], bl[3]);
                }
                // lh term
#pragma unroll
                for (int mt = 0; mt < 4; ++mt) {
                    mma_bf16(acc[mt][2 * p],     al[mt], bh[0], bh[1]);
                    mma_bf16(acc[mt][2 * p + 1], al[mt], bh[2], bh[3]);
                }
            }
        }
    }
#undef T_LOAD

    // epilogue
#pragma unroll
    for (int mt = 0; mt < 4; ++mt) {
#pragma unroll
        for (int nt = 0; nt < 8; ++nt) {
            const int rr = m0 + wm * 64 + mt * 16 + (lane >> 2);
            const int cc = n0 + wn * 64 + nt * 8 + ((lane & 3) << 1);
            const float2 bv = *(const float2*)&bias[cc];
            const float o00 = acc[mt][nt][0] + bv.x;
            const float o01 = acc[mt][nt][1] + bv.y;
            const float o10 = acc[mt][nt][2] + bv.x;
            const float o11 = acc[mt][nt][3] + bv.y;
            if (mode == 1) {
                float2 a = {o00, o01}, b = {o10, o11};
                *(float2*)&Cf[(size_t)rr * DIMN + cc]       = a;
                *(float2*)&Cf[(size_t)(rr + 8) * DIMN + cc] = b;
            } else {
                const int h = cc >> 6, hd = cc & 63;
                {
                    const int b = rr >> 11, l = rr & 2047;
                    size_t d = ((((size_t)b * NUM_HEADS + h) * SEQ + l) * HEAD_DIM + hd);
                    *(__half2*)&Ch[d] = __floats2half2_rn(o00 * scale, o01 * scale);
                }
                {
                    const int r2 = rr + 8;
                    const int b = r2 >> 11, l = r2 & 2047;
                    size_t d = ((((size_t)b * NUM_HEADS + h) * SEQ + l) * HEAD_DIM + hd);
                    *(__half2*)&Ch[d] = __floats2half2_rn(o10 * scale, o11 * scale);
                }
            }
        }
    }
}

// ---------------------------------------------------------------------------
// Tensor-core flash attention (R6, proven): 256 threads (8 warps, 16 q/warp),
// fp16 MMA, fp32 accum, 3-stage cp.async. Output split bf16 hi/lo [B,L,D].
// ---------------------------------------------------------------------------
#define ASTR     72
#define A_STAGES 3

struct AttnStage {
    __half Ks[64 * ASTR];
    __half Vs[64 * ASTR];
    int    Ms[64];
};
#define A_SMEM (A_STAGES * (int)sizeof(AttnStage))

__global__ __launch_bounds__(256, 2)
void attn_mma_kernel(const __half* __restrict__ Qh, const __half* __restrict__ Kh,
                     const __half* __restrict__ Vh, const int* __restrict__ kv_mask,
                     __nv_bfloat16* __restrict__ OutH,
                     __nv_bfloat16* __restrict__ OutL)
{
    extern __shared__ char asm_raw[];
    AttnStage* stg = (AttnStage*)asm_raw;

    const int tid  = threadIdx.x;
    const int lane = tid & 31;
    const int wid  = tid >> 5;
    const int bh   = blockIdx.y;
    const int b    = bh >> 4;
    const int h    = bh & 15;
    const int q0   = blockIdx.x * 128 + wid * 16;

    const __half* Kb = Kh + (size_t)bh * SEQ * HEAD_DIM;
    const __half* Vb = Vh + (size_t)bh * SEQ * HEAD_DIM;
    const int*    Mb = kv_mask + b * SEQ;

#define A_ISSUE(J0, ST)                                                        \
    do {                                                                       \
        uint32_t sK_ = smem_cast(stg[ST].Ks);                                  \
        uint32_t sV_ = smem_cast(stg[ST].Vs);                                  \
        uint32_t sM_ = smem_cast(stg[ST].Ms);                                  \
        for (int idx = tid; idx < 1040; idx += 256) {                          \
            if (idx < 512) {                                                   \
                int rr = idx >> 3, cc = idx & 7;                               \
                cp16(sK_ + (uint32_t)(rr * ASTR + cc * 8) * 2,                 \
                     Kb + (size_t)((J0) + rr) * HEAD_DIM + cc * 8);            \
            } else if (idx < 1024) {                                           \
                int q = idx - 512, rr = q >> 3, cc = q & 7;                    \
                cp16(sV_ + (uint32_t)(rr * ASTR + cc * 8) * 2,                 \
                     Vb + (size_t)((J0) + rr) * HEAD_DIM + cc * 8);            \
            } else {                                                           \
                int q = idx - 1024;                                            \
                cp16(sM_ + (uint32_t)q * 16, Mb + (J0) + q * 4);               \
            }                                                                  \
        }                                                                      \
    } while (0)

    A_ISSUE(0, 0);  cp_commit();
    A_ISSUE(64, 1); cp_commit();

    uint32_t aq[4][4];
    {
        const __half* Qb = Qh + (size_t)bh * SEQ * HEAD_DIM;
#pragma unroll
        for (int ks = 0; ks < 4; ++ks)
#pragma unroll
            for (int j = 0; j < 4; ++j) {
                const int rr = q0 + (lane >> 2) + (j & 1) * 8;
                const int cc = ks * 16 + ((j >> 1) << 3) + ((lane & 3) << 1);
                aq[ks][j] = *(const uint32_t*)&Qb[(size_t)rr * HEAD_DIM + cc];
            }
    }

    float O[8][4];
#pragma unroll
    for (int i = 0; i < 8; ++i)
#pragma unroll
        for (int j = 0; j < 4; ++j) O[i][j] = 0.0f;
    float m0r = -1e30f, m1r = -1e30f, l0r = 0.0f, l1r = 0.0f;

    const uint32_t kfrag =
        (uint32_t)(((((lane >> 4) << 3) + (lane & 7)) * ASTR + ((lane >> 3) & 1) * 8)) * 2;
    const uint32_t vfrag =
        (uint32_t)((((((lane >> 3) & 1) << 3) + (lane & 7)) * ASTR + (lane >> 4) * 8)) * 2;

    const int NT = SEQ / 64;
    for (int kt = 0; kt < NT; ++kt) {
        cp_wait<1>();
        __syncthreads();
        if (kt + 2 < NT) A_ISSUE((kt + 2) * 64, (kt + 2) % A_STAGES);
        cp_commit();

        AttnStage* st = &stg[kt % A_STAGES];
        const uint32_t aK = smem_cast(st->Ks);
        const uint32_t aV = smem_cast(st->Vs);

        float S[8][4];
#pragma unroll
        for (int i = 0; i < 8; ++i)
#pragma unroll
            for (int j = 0; j < 4; ++j) S[i][j] = 0.0f;
#pragma unroll
        for (int ks = 0; ks < 4; ++ks) {
#pragma unroll
            for (int p = 0; p < 4; ++p) {
                uint32_t bq[4];
                ldsm4(bq[0], bq[1], bq[2], bq[3],
                      aK + kfrag + (uint32_t)(p * 16 * ASTR * 2 + ks * 32));
                mma_f16(S[2 * p],     aq[ks], bq[0], bq[1]);
                mma_f16(S[2 * p + 1], aq[ks], bq[2], bq[3]);
            }
        }

        float mx0 = -1e30f, mx1 = -1e30f;
#pragma unroll
        for (int nt = 0; nt < 8; ++nt) {
            const int kk = nt * 8 + ((lane & 3) << 1);
            const int2 mi = *(const int2*)&st->Ms[kk];
            const float mdx = mi.x ? 0.0f : -1e30f;
            const float mdy = mi.y ? 0.0f : -1e30f;
            S[nt][0] += mdx; S[nt][1] += mdy;
            S[nt][2] += mdx; S[nt][3] += mdy;
            mx0 = fmaxf(mx0, fmaxf(S[nt][0], S[nt][1]));
            mx1 = fmaxf(mx1, fmaxf(S[nt][2], S[nt][3]));
        }
        mx0 = fmaxf(mx0, __shfl_xor_sync(0xffffffffu, mx0, 1));
        mx0 = fmaxf(mx0, __shfl_xor_sync(0xffffffffu, mx0, 2));
        mx1 = fmaxf(mx1, __shfl_xor_sync(0xffffffffu, mx1, 1));
        mx1 = fmaxf(mx1, __shfl_xor_sync(0xffffffffu, mx1, 2));

        const float nm0 = fmaxf(m0r, mx0), nm1 = fmaxf(m1r, mx1);
        const float f0 = __expf(m0r - nm0), f1 = __expf(m1r - nm1);
        m0r = nm0; m1r = nm1;

        float s0 = 0.0f, s1 = 0.0f;
#pragma unroll
        for (int nt = 0; nt < 8; ++nt) {
            S[nt][0] = __expf(S[nt][0] - nm0);
            S[nt][1] = __expf(S[nt][1] - nm0);
            S[nt][2] = __expf(S[nt][2] - nm1);
            S[nt][3] = __expf(S[nt][3] - nm1);
            s0 += S[nt][0] + S[nt][1];
            s1 += S[nt][2] + S[nt][3];
        }
        s0 += __shfl_xor_sync(0xffffffffu, s0, 1);
        s0 += __shfl_xor_sync(0xffffffffu, s0, 2);
        s1 += __shfl_xor_sync(0xffffffffu, s1, 1);
        s1 += __shfl_xor_sync(0xffffffffu, s1, 2);
        l0r = l0r * f0 + s0;
        l1r = l1r * f1 + s1;

#pragma unroll
        for (int nt = 0; nt < 8; ++nt) {
            O[nt][0] *= f0; O[nt][1] *= f0;
            O[nt][2] *= f1; O[nt][3] *= f1;
        }

#pragma unroll
        for (int ks = 0; ks < 4; ++ks) {
            uint32_t pa[4];
            {
                __half2 t0 = __floats2half2_rn(S[2 * ks][0],     S[2 * ks][1]);
                __half2 t1 = __floats2half2_rn(S[2 * ks][2],     S[2 * ks][3]);
                __half2 t2 = __floats2half2_rn(S[2 * ks + 1][0], S[2 * ks + 1][1]);
                __half2 t3 = __floats2half2_rn(S[2 * ks + 1][2], S[2 * ks + 1][3]);
                pa[0] = *(uint32_t*)&t0; pa[1] = *(uint32_t*)&t1;
                pa[2] = *(uint32_t*)&t2; pa[3] = *(uint32_t*)&t3;
            }
#pragma unroll
            for (int p = 0; p < 4; ++p) {
                uint32_t bv[4];
                ldsm4t(bv[0], bv[1], bv[2], bv[3],
                       aV + vfrag + (uint32_t)(ks * 16 * ASTR * 2 + p * 32));
                mma_f16(O[2 * p],     pa, bv[0], bv[1]);
                mma_f16(O[2 * p + 1], pa, bv[2], bv[3]);
            }
        }
    }
#undef A_ISSUE

    const float inv0 = 1.0f / l0r, inv1 = 1.0f / l1r;
    const int qr = q0 + (lane >> 2);
    const size_t base0 = ((size_t)b * SEQ + qr) * DIMN + h * HEAD_DIM;
    const size_t base1 = ((size_t)b * SEQ + qr + 8) * DIMN + h * HEAD_DIM;
#pragma unroll
    for (int nt = 0; nt < 8; ++nt) {
        const int c = nt * 8 + ((lane & 3) << 1);
        __nv_bfloat162 h0, l0, h1, l1;
        split2(O[nt][0] * inv0, O[nt][1] * inv0, h0, l0);
        split2(O[nt][2] * inv1, O[nt][3] * inv1, h1, l1);
        *(__nv_bfloat162*)&OutH[base0 + c] = h0;
        *(__nv_bfloat162*)&OutL[base0 + c] = l0;
        *(__nv_bfloat162*)&OutH[base1 + c] = h1;
        *(__nv_bfloat162*)&OutL[base1 + c] = l1;
    }
}

// ---------------------------------------------------------------------------
extern "C" void kernel_launch(void* const* d_in, const int* in_sizes, int n_in,
                              void* d_out, int out_size)
{
    const float* q    = (const float*)d_in[0];
    const float* k    = (const float*)d_in[1];
    const float* v    = (const float*)d_in[2];
    const int*   mask = (const int*)  d_in[3];
    const float* Wq   = (const float*)d_in[4];
    const float* bq   = (const float*)d_in[5];
    const float* Wk   = (const float*)d_in[6];
    const float* bk   = (const float*)d_in[7];
    const float* Wv   = (const float*)d_in[8];
    const float* bv   = (const float*)d_in[9];
    const float* Wo   = (const float*)d_in[10];
    const float* bo   = (const float*)d_in[11];
    float*       out  = (float*)d_out;

    static bool attr_done = false;
    if (!attr_done) {
        cudaFuncSetAttribute(gemm_ts_kernel,
                             cudaFuncAttributeMaxDynamicSharedMemorySize, T_SMEM);
        cudaFuncSetAttribute(attn_mma_kernel,
                             cudaFuncAttributeMaxDynamicSharedMemorySize, A_SMEM);
        attr_done = true;
    }

    void *p_xh, *p_xl, *p_wh, *p_wl, *p_q16, *p_k16, *p_v16, *p_ah, *p_al;
    cudaGetSymbolAddress(&p_xh,  g_xh);
    cudaGetSymbolAddress(&p_xl,  g_xl);
    cudaGetSymbolAddress(&p_wh,  g_wh);
    cudaGetSymbolAddress(&p_wl,  g_wl);
    cudaGetSymbolAddress(&p_q16, g_q16);
    cudaGetSymbolAddress(&p_k16, g_k16);
    cudaGetSymbolAddress(&p_v16, g_v16);
    cudaGetSymbolAddress(&p_ah,  g_ah);
    cudaGetSymbolAddress(&p_al,  g_al);

    __nv_bfloat16* xh = (__nv_bfloat16*)p_xh;
    __nv_bfloat16* xl = (__nv_bfloat16*)p_xl;
    __nv_bfloat16* wh = (__nv_bfloat16*)p_wh;
    __nv_bfloat16* wl = (__nv_bfloat16*)p_wl;

    split_kernel<<<dim3(NELEM / 1024, 3), 256>>>(q, k, v, nullptr, xh, xl, NELEM);
    split_kernel<<<dim3(WELEM / 1024, 4), 256>>>(Wq, Wk, Wv, Wo, wh, wl, WELEM);

    dim3 gg(DIMN / 128, MROWS / 256);   // (8, 16) = 128 CTAs, one wave
    gemm_ts_kernel<<<gg, 256, T_SMEM>>>(xh, xl, wh, wl, bq,
                                        (__half*)p_q16, nullptr, QK_SCALE, 0);
    gemm_ts_kernel<<<gg, 256, T_SMEM>>>(xh + (size_t)NELEM, xl + (size_t)NELEM,
                                        wh + (size_t)WELEM, wl + (size_t)WELEM, bk,
                                        (__half*)p_k16, nullptr, 1.0f, 0);
    gemm_ts_kernel<<<gg, 256, T_SMEM>>>(xh + 2 * (size_t)NELEM, xl + 2 * (size_t)NELEM,
                                        wh + 2 * (size_t)WELEM, wl + 2 * (size_t)WELEM, bv,
                                        (__half*)p_v16, nullptr, 1.0f, 0);

    dim3 ag(SEQ / 128, BATCH * NUM_HEADS);   // (16, 32)
    attn_mma_kernel<<<ag, 256, A_SMEM>>>((const __half*)p_q16, (const __half*)p_k16,
                                         (const __half*)p_v16, mask,
                                         (__nv_bfloat16*)p_ah, (__nv_bfloat16*)p_al);

    gemm_ts_kernel<<<gg, 256, T_SMEM>>>((__nv_bfloat16*)p_ah, (__nv_bfloat16*)p_al,
                                        wh + 3 * (size_t)WELEM, wl + 3 * (size_t)WELEM, bo,
                                        nullptr, out, 1.0f, 1);
}

// round 16
// speedup vs baseline: 2.3674x; 1.5975x over previous
#include <cuda_runtime.h>
#include <cuda_bf16.h>
#include <cuda_fp16.h>
#include <stdint.h>

// Problem constants
#define DIMN      1024
#define NUM_HEADS 16
#define HEAD_DIM  64
#define BATCH     2
#define SEQ       2048
#define MROWS     (BATCH * SEQ)          // 4096
#define NELEM     (MROWS * DIMN)         // 4,194,304
#define WELEM     (DIMN * DIMN)          // 1,048,576
#define QK_SCALE  0.125f

// ---------------- scratch (static device globals; no allocation) -----------
__device__ __half g_x16[3 * NELEM];   // fp16 q,k,v inputs [B,L,D]
__device__ __half g_w16[4 * WELEM];   // fp16 Wq,Wk,Wv,Wo
__device__ __half g_q16[NELEM];       // fp16 [B,H,L,hd], pre-scaled
__device__ __half g_k16[NELEM];
__device__ __half g_v16[NELEM];
__device__ __half g_a16[NELEM];       // attn output fp16 [B,L,D]

// ---------------------------------------------------------------------------
// PTX helpers
// ---------------------------------------------------------------------------
__device__ __forceinline__ uint32_t smem_cast(const void* p) {
    return (uint32_t)__cvta_generic_to_shared(p);
}
__device__ __forceinline__ void cp16(uint32_t s, const void* g) {
    asm volatile("cp.async.cg.shared.global [%0], [%1], 16;" :: "r"(s), "l"(g));
}
__device__ __forceinline__ void cp_commit() {
    asm volatile("cp.async.commit_group;");
}
template <int N>
__device__ __forceinline__ void cp_wait() {
    asm volatile("cp.async.wait_group %0;" :: "n"(N));
}
__device__ __forceinline__ void ldsm4(uint32_t& d0, uint32_t& d1, uint32_t& d2,
                                      uint32_t& d3, uint32_t a) {
    asm volatile("ldmatrix.sync.aligned.m8n8.x4.shared.b16 {%0,%1,%2,%3},[%4];"
                 : "=r"(d0), "=r"(d1), "=r"(d2), "=r"(d3) : "r"(a));
}
__device__ __forceinline__ void ldsm4t(uint32_t& d0, uint32_t& d1, uint32_t& d2,
                                       uint32_t& d3, uint32_t a) {
    asm volatile("ldmatrix.sync.aligned.m8n8.x4.trans.shared.b16 {%0,%1,%2,%3},[%4];"
                 : "=r"(d0), "=r"(d1), "=r"(d2), "=r"(d3) : "r"(a));
}
__device__ __forceinline__ void mma_f16(float* c, const uint32_t* a,
                                        uint32_t b0, uint32_t b1) {
    asm volatile(
        "mma.sync.aligned.m16n8k16.row.col.f32.f16.f16.f32 "
        "{%0,%1,%2,%3},{%4,%5,%6,%7},{%8,%9},{%0,%1,%2,%3};"
        : "+f"(c[0]), "+f"(c[1]), "+f"(c[2]), "+f"(c[3])
        : "r"(a[0]), "r"(a[1]), "r"(a[2]), "r"(a[3]), "r"(b0), "r"(b1));
}

// ---------------------------------------------------------------------------
// Convert kernel: fp32 -> fp16, up to 4 tensors selected by blockIdx.y.
// ---------------------------------------------------------------------------
__global__ __launch_bounds__(256)
void cvt_kernel(const float* __restrict__ S0, const float* __restrict__ S1,
                const float* __restrict__ S2, const float* __restrict__ S3,
                __half* __restrict__ D, int n_per)
{
    const int t = blockIdx.y;
    const float* S = (t == 0) ? S0 : (t == 1) ? S1 : (t == 2) ? S2 : S3;
    const int i = (blockIdx.x * 256 + threadIdx.x) * 4;
    if (i >= n_per) return;
    const size_t base = (size_t)t * n_per + i;
    float4 v = *(const float4*)(S + i);
    __half2 h0 = __floats2half2_rn(v.x, v.y);
    __half2 h1 = __floats2half2_rn(v.z, v.w);
    uint2 hp;
    hp.x = *(uint32_t*)&h0; hp.y = *(uint32_t*)&h1;
    *(uint2*)(D + base) = hp;
}

// ---------------------------------------------------------------------------
// fp16 tensor-core GEMM: C = A[M,K] @ W[N,K]^T + bias
// CTA tile 256x128, 256 threads, 8 warps as 4m x 2n with 64x64 warp tiles,
// BK=32, 3-stage cp.async (92KB smem), grid (8,16) = 128 CTAs.
// mode 0: C fp16 head-split [B,H,L,hd], scaled.  mode 1: C fp32 flat [M,N].
// ---------------------------------------------------------------------------
#define GSTR      40                        // smem row stride in fp16 (80B)
#define T_A_ELE   (256 * GSTR)              // 10240 fp16 (256x32 tile)
#define T_W_ELE   (128 * GSTR)              // 5120  fp16 (128x32 tile)
#define T_STG_B   ((T_A_ELE + T_W_ELE) * 2) // 30720 bytes
#define T_STAGES  3
#define T_SMEM    (T_STAGES * T_STG_B)      // 92160 bytes

__global__ __launch_bounds__(256, 1)
void gemm_f16_kernel(const __half* __restrict__ A,
                     const __half* __restrict__ W,
                     const float* __restrict__ bias,
                     __half* __restrict__ Ch, float* __restrict__ Cf,
                     float scale, int mode)
{
    extern __shared__ __half sg[];
    const int tid  = threadIdx.x;
    const int lane = tid & 31;
    const int wid  = tid >> 5;
    const int wm   = wid & 3;        // 4 m-warps x 64 rows
    const int wn   = wid >> 2;       // 2 n-warps x 64 cols
    const int m0   = blockIdx.y * 256;
    const int n0   = blockIdx.x * 128;

    const uint32_t sbase = smem_cast(sg);

    // cp.async mapping: idx -> row idx>>2, col (idx&3)*8
    const int ar = tid >> 2;              // 0..63 (+i*64)
    const int ac = (tid & 3) << 3;        // 0,8,16,24

    float acc[4][8][4];
#pragma unroll
    for (int i = 0; i < 4; ++i)
#pragma unroll
        for (int j = 0; j < 8; ++j)
#pragma unroll
            for (int q = 0; q < 4; ++q) acc[i][j][q] = 0.0f;

    // ldmatrix offsets (bytes, within one matrix region)
    const uint32_t aoff = (uint32_t)((wm * 64 + (lane & 15)) * GSTR +
                                     (lane >> 4) * 8) * 2;
    const int bn = wn * 64 + ((lane >> 4) << 3) + (lane & 7);
    const uint32_t boff = (uint32_t)(bn * GSTR + ((lane >> 3) & 1) * 8) * 2;

#define T_LOAD(KT, ST)                                                        \
    do {                                                                      \
        const uint32_t sb_ = sbase + (uint32_t)(ST) * T_STG_B;                \
        const int kc0 = (KT) * 32;                                            \
        _Pragma("unroll")                                                     \
        for (int i = 0; i < 4; ++i) {                                         \
            const int r = ar + i * 64;                                        \
            const uint32_t so = (uint32_t)(r * GSTR + ac) * 2;                \
            cp16(sb_ + so, A + (size_t)(m0 + r) * DIMN + kc0 + ac);           \
        }                                                                     \
        _Pragma("unroll")                                                     \
        for (int i = 0; i < 2; ++i) {                                         \
            const int r = ar + i * 64;                                        \
            const uint32_t so = (uint32_t)(r * GSTR + ac) * 2;                \
            cp16(sb_ + T_A_ELE * 2 + so, W + (size_t)(n0 + r) * DIMN + kc0 + ac); \
        }                                                                     \
    } while (0)

    // prologue: stages 0,1
    T_LOAD(0, 0); cp_commit();
    T_LOAD(1, 1); cp_commit();

    const int NKT = DIMN / 32;   // 32
    for (int kt = 0; kt < NKT; ++kt) {
        cp_wait<1>();
        __syncthreads();
        if (kt + 2 < NKT) T_LOAD(kt + 2, (kt + 2) % 3);
        cp_commit();

        const uint32_t sb = sbase + (uint32_t)(kt % 3) * T_STG_B;
        const uint32_t aA = sb;
        const uint32_t aB = sb + T_A_ELE * 2;

#pragma unroll
        for (int ks = 0; ks < 2; ++ks) {
            const uint32_t ko = (uint32_t)ks * 32;   // 16 fp16 = 32 bytes
            uint32_t ah[4][4];
#pragma unroll
            for (int mt = 0; mt < 4; ++mt) {
                const uint32_t mo = (uint32_t)(mt * 16 * GSTR) * 2 + ko;
                ldsm4(ah[mt][0], ah[mt][1], ah[mt][2], ah[mt][3], aA + aoff + mo);
            }
#pragma unroll
            for (int p = 0; p < 4; ++p) {
                uint32_t bh[4];
                const uint32_t po = (uint32_t)(p * 16 * GSTR) * 2 + ko;
                ldsm4(bh[0], bh[1], bh[2], bh[3], aB + boff + po);
#pragma unroll
                for (int mt = 0; mt < 4; ++mt) {
                    mma_f16(acc[mt][2 * p],     ah[mt], bh[0], bh[1]);
                    mma_f16(acc[mt][2 * p + 1], ah[mt], bh[2], bh[3]);
                }
            }
        }
    }
#undef T_LOAD

    // epilogue
#pragma unroll
    for (int mt = 0; mt < 4; ++mt) {
#pragma unroll
        for (int nt = 0; nt < 8; ++nt) {
            const int rr = m0 + wm * 64 + mt * 16 + (lane >> 2);
            const int cc = n0 + wn * 64 + nt * 8 + ((lane & 3) << 1);
            const float2 bv = *(const float2*)&bias[cc];
            const float o00 = acc[mt][nt][0] + bv.x;
            const float o01 = acc[mt][nt][1] + bv.y;
            const float o10 = acc[mt][nt][2] + bv.x;
            const float o11 = acc[mt][nt][3] + bv.y;
            if (mode == 1) {
                float2 a = {o00, o01}, b = {o10, o11};
                *(float2*)&Cf[(size_t)rr * DIMN + cc]       = a;
                *(float2*)&Cf[(size_t)(rr + 8) * DIMN + cc] = b;
            } else {
                const int h = cc >> 6, hd = cc & 63;
                {
                    const int b = rr >> 11, l = rr & 2047;
                    size_t d = ((((size_t)b * NUM_HEADS + h) * SEQ + l) * HEAD_DIM + hd);
                    *(__half2*)&Ch[d] = __floats2half2_rn(o00 * scale, o01 * scale);
                }
                {
                    const int r2 = rr + 8;
                    const int b = r2 >> 11, l = r2 & 2047;
                    size_t d = ((((size_t)b * NUM_HEADS + h) * SEQ + l) * HEAD_DIM + hd);
                    *(__half2*)&Ch[d] = __floats2half2_rn(o10 * scale, o11 * scale);
                }
            }
        }
    }
}

// ---------------------------------------------------------------------------
// Tensor-core flash attention (proven): 256 threads (8 warps, 16 q/warp),
// fp16 MMA, fp32 accum, 3-stage cp.async. Output fp16 [B,L,D].
// ---------------------------------------------------------------------------
#define ASTR     72
#define A_STAGES 3

struct AttnStage {
    __half Ks[64 * ASTR];
    __half Vs[64 * ASTR];
    int    Ms[64];
};
#define A_SMEM (A_STAGES * (int)sizeof(AttnStage))

__global__ __launch_bounds__(256, 2)
void attn_mma_kernel(const __half* __restrict__ Qh, const __half* __restrict__ Kh,
                     const __half* __restrict__ Vh, const int* __restrict__ kv_mask,
                     __half* __restrict__ Out)
{
    extern __shared__ char asm_raw[];
    AttnStage* stg = (AttnStage*)asm_raw;

    const int tid  = threadIdx.x;
    const int lane = tid & 31;
    const int wid  = tid >> 5;
    const int bh   = blockIdx.y;
    const int b    = bh >> 4;
    const int h    = bh & 15;
    const int q0   = blockIdx.x * 128 + wid * 16;

    const __half* Kb = Kh + (size_t)bh * SEQ * HEAD_DIM;
    const __half* Vb = Vh + (size_t)bh * SEQ * HEAD_DIM;
    const int*    Mb = kv_mask + b * SEQ;

#define A_ISSUE(J0, ST)                                                        \
    do {                                                                       \
        uint32_t sK_ = smem_cast(stg[ST].Ks);                                  \
        uint32_t sV_ = smem_cast(stg[ST].Vs);                                  \
        uint32_t sM_ = smem_cast(stg[ST].Ms);                                  \
        for (int idx = tid; idx < 1040; idx += 256) {                          \
            if (idx < 512) {                                                   \
                int rr = idx >> 3, cc = idx & 7;                               \
                cp16(sK_ + (uint32_t)(rr * ASTR + cc * 8) * 2,                 \
                     Kb + (size_t)((J0) + rr) * HEAD_DIM + cc * 8);            \
            } else if (idx < 1024) {                                           \
                int q = idx - 512, rr = q >> 3, cc = q & 7;                    \
                cp16(sV_ + (uint32_t)(rr * ASTR + cc * 8) * 2,                 \
                     Vb + (size_t)((J0) + rr) * HEAD_DIM + cc * 8);            \
            } else {                                                           \
                int q = idx - 1024;                                            \
                cp16(sM_ + (uint32_t)q * 16, Mb + (J0) + q * 4);               \
            }                                                                  \
        }                                                                      \
    } while (0)

    A_ISSUE(0, 0);  cp_commit();
    A_ISSUE(64, 1); cp_commit();

    uint32_t aq[4][4];
    {
        const __half* Qb = Qh + (size_t)bh * SEQ * HEAD_DIM;
#pragma unroll
        for (int ks = 0; ks < 4; ++ks)
#pragma unroll
            for (int j = 0; j < 4; ++j) {
                const int rr = q0 + (lane >> 2) + (j & 1) * 8;
                const int cc = ks * 16 + ((j >> 1) << 3) + ((lane & 3) << 1);
                aq[ks][j] = *(const uint32_t*)&Qb[(size_t)rr * HEAD_DIM + cc];
            }
    }

    float O[8][4];
#pragma unroll
    for (int i = 0; i < 8; ++i)
#pragma unroll
        for (int j = 0; j < 4; ++j) O[i][j] = 0.0f;
    float m0r = -1e30f, m1r = -1e30f, l0r = 0.0f, l1r = 0.0f;

    const uint32_t kfrag =
        (uint32_t)(((((lane >> 4) << 3) + (lane & 7)) * ASTR + ((lane >> 3) & 1) * 8)) * 2;
    const uint32_t vfrag =
        (uint32_t)((((((lane >> 3) & 1) << 3) + (lane & 7)) * ASTR + (lane >> 4) * 8)) * 2;

    const int NT = SEQ / 64;
    for (int kt = 0; kt < NT; ++kt) {
        cp_wait<1>();
        __syncthreads();
        if (kt + 2 < NT) A_ISSUE((kt + 2) * 64, (kt + 2) % A_STAGES);
        cp_commit();

        AttnStage* st = &stg[kt % A_STAGES];
        const uint32_t aK = smem_cast(st->Ks);
        const uint32_t aV = smem_cast(st->Vs);

        float S[8][4];
#pragma unroll
        for (int i = 0; i < 8; ++i)
#pragma unroll
            for (int j = 0; j < 4; ++j) S[i][j] = 0.0f;
#pragma unroll
        for (int ks = 0; ks < 4; ++ks) {
#pragma unroll
            for (int p = 0; p < 4; ++p) {
                uint32_t bq[4];
                ldsm4(bq[0], bq[1], bq[2], bq[3],
                      aK + kfrag + (uint32_t)(p * 16 * ASTR * 2 + ks * 32));
                mma_f16(S[2 * p],     aq[ks], bq[0], bq[1]);
                mma_f16(S[2 * p + 1], aq[ks], bq[2], bq[3]);
            }
        }

        float mx0 = -1e30f, mx1 = -1e30f;
#pragma unroll
        for (int nt = 0; nt < 8; ++nt) {
            const int kk = nt * 8 + ((lane & 3) << 1);
            const int2 mi = *(const int2*)&st->Ms[kk];
            const float mdx = mi.x ? 0.0f : -1e30f;
            const float mdy = mi.y ? 0.0f : -1e30f;
            S[nt][0] += mdx; S[nt][1] += mdy;
            S[nt][2] += mdx; S[nt][3] += mdy;
            mx0 = fmaxf(mx0, fmaxf(S[nt][0], S[nt][1]));
            mx1 = fmaxf(mx1, fmaxf(S[nt][2], S[nt][3]));
        }
        mx0 = fmaxf(mx0, __shfl_xor_sync(0xffffffffu, mx0, 1));
        mx0 = fmaxf(mx0, __shfl_xor_sync(0xffffffffu, mx0, 2));
        mx1 = fmaxf(mx1, __shfl_xor_sync(0xffffffffu, mx1, 1));
        mx1 = fmaxf(mx1, __shfl_xor_sync(0xffffffffu, mx1, 2));

        const float nm0 = fmaxf(m0r, mx0), nm1 = fmaxf(m1r, mx1);
        const float f0 = __expf(m0r - nm0), f1 = __expf(m1r - nm1);
        m0r = nm0; m1r = nm1;

        float s0 = 0.0f, s1 = 0.0f;
#pragma unroll
        for (int nt = 0; nt < 8; ++nt) {
            S[nt][0] = __expf(S[nt][0] - nm0);
            S[nt][1] = __expf(S[nt][1] - nm0);
            S[nt][2] = __expf(S[nt][2] - nm1);
            S[nt][3] = __expf(S[nt][3] - nm1);
            s0 += S[nt][0] + S[nt][1];
            s1 += S[nt][2] + S[nt][3];
        }
        s0 += __shfl_xor_sync(0xffffffffu, s0, 1);
        s0 += __shfl_xor_sync(0xffffffffu, s0, 2);
        s1 += __shfl_xor_sync(0xffffffffu, s1, 1);
        s1 += __shfl_xor_sync(0xffffffffu, s1, 2);
        l0r = l0r * f0 + s0;
        l1r = l1r * f1 + s1;

#pragma unroll
        for (int nt = 0; nt < 8; ++nt) {
            O[nt][0] *= f0; O[nt][1] *= f0;
            O[nt][2] *= f1; O[nt][3] *= f1;
        }

#pragma unroll
        for (int ks = 0; ks < 4; ++ks) {
            uint32_t pa[4];
            {
                __half2 t0 = __floats2half2_rn(S[2 * ks][0],     S[2 * ks][1]);
                __half2 t1 = __floats2half2_rn(S[2 * ks][2],     S[2 * ks][3]);
                __half2 t2 = __floats2half2_rn(S[2 * ks + 1][0], S[2 * ks + 1][1]);
                __half2 t3 = __floats2half2_rn(S[2 * ks + 1][2], S[2 * ks + 1][3]);
                pa[0] = *(uint32_t*)&t0; pa[1] = *(uint32_t*)&t1;
                pa[2] = *(uint32_t*)&t2; pa[3] = *(uint32_t*)&t3;
            }
#pragma unroll
            for (int p = 0; p < 4; ++p) {
                uint32_t bv[4];
                ldsm4t(bv[0], bv[1], bv[2], bv[3],
                       aV + vfrag + (uint32_t)(ks * 16 * ASTR * 2 + p * 32));
                mma_f16(O[2 * p],     pa, bv[0], bv[1]);
                mma_f16(O[2 * p + 1], pa, bv[2], bv[3]);
            }
        }
    }
#undef A_ISSUE

    const float inv0 = 1.0f / l0r, inv1 = 1.0f / l1r;
    const int qr = q0 + (lane >> 2);
    const size_t base0 = ((size_t)b * SEQ + qr) * DIMN + h * HEAD_DIM;
    const size_t base1 = ((size_t)b * SEQ + qr + 8) * DIMN + h * HEAD_DIM;
#pragma unroll
    for (int nt = 0; nt < 8; ++nt) {
        const int c = nt * 8 + ((lane & 3) << 1);
        *(__half2*)&Out[base0 + c] = __floats2half2_rn(O[nt][0] * inv0, O[nt][1] * inv0);
        *(__half2*)&Out[base1 + c] = __floats2half2_rn(O[nt][2] * inv1, O[nt][3] * inv1);
    }
}

// ---------------------------------------------------------------------------
extern "C" void kernel_launch(void* const* d_in, const int* in_sizes, int n_in,
                              void* d_out, int out_size)
{
    const float* q    = (const float*)d_in[0];
    const float* k    = (const float*)d_in[1];
    const float* v    = (const float*)d_in[2];
    const int*   mask = (const int*)  d_in[3];
    const float* Wq   = (const float*)d_in[4];
    const float* bq   = (const float*)d_in[5];
    const float* Wk   = (const float*)d_in[6];
    const float* bk   = (const float*)d_in[7];
    const float* Wv   = (const float*)d_in[8];
    const float* bv   = (const float*)d_in[9];
    const float* Wo   = (const float*)d_in[10];
    const float* bo   = (const float*)d_in[11];
    float*       out  = (float*)d_out;

    static bool attr_done = false;
    if (!attr_done) {
        cudaFuncSetAttribute(gemm_f16_kernel,
                             cudaFuncAttributeMaxDynamicSharedMemorySize, T_SMEM);
        cudaFuncSetAttribute(attn_mma_kernel,
                             cudaFuncAttributeMaxDynamicSharedMemorySize, A_SMEM);
        attr_done = true;
    }

    void *p_x16, *p_w16, *p_q16, *p_k16, *p_v16, *p_a16;
    cudaGetSymbolAddress(&p_x16, g_x16);
    cudaGetSymbolAddress(&p_w16, g_w16);
    cudaGetSymbolAddress(&p_q16, g_q16);
    cudaGetSymbolAddress(&p_k16, g_k16);
    cudaGetSymbolAddress(&p_v16, g_v16);
    cudaGetSymbolAddress(&p_a16, g_a16);

    __half* x16 = (__half*)p_x16;
    __half* w16 = (__half*)p_w16;

    // convert inputs (3 x 4M) and weights (4 x 1M) to fp16
    cvt_kernel<<<dim3(NELEM / 1024, 3), 256>>>(q, k, v, nullptr, x16, NELEM);
    cvt_kernel<<<dim3(WELEM / 1024, 4), 256>>>(Wq, Wk, Wv, Wo, w16, WELEM);

    dim3 gg(DIMN / 128, MROWS / 256);   // (8, 16) = 128 CTAs
    gemm_f16_kernel<<<gg, 256, T_SMEM>>>(x16, w16, bq,
                                         (__half*)p_q16, nullptr, QK_SCALE, 0);
    gemm_f16_kernel<<<gg, 256, T_SMEM>>>(x16 + (size_t)NELEM,
                                         w16 + (size_t)WELEM, bk,
                                         (__half*)p_k16, nullptr, 1.0f, 0);
    gemm_f16_kernel<<<gg, 256, T_SMEM>>>(x16 + 2 * (size_t)NELEM,
                                         w16 + 2 * (size_t)WELEM, bv,
                                         (__half*)p_v16, nullptr, 1.0f, 0);

    dim3 ag(SEQ / 128, BATCH * NUM_HEADS);   // (16, 32)
    attn_mma_kernel<<<ag, 256, A_SMEM>>>((const __half*)p_q16, (const __half*)p_k16,
                                         (const __half*)p_v16, mask,
                                         (__half*)p_a16);

    gemm_f16_kernel<<<gg, 256, T_SMEM>>>((const __half*)p_a16,
                                         w16 + 3 * (size_t)WELEM, bo,
                                         nullptr, out, 1.0f, 1);
}

// round 17
// speedup vs baseline: 2.4227x; 1.0233x over previous
#include <cuda_runtime.h>
#include <cuda_bf16.h>
#include <cuda_fp16.h>
#include <stdint.h>

// Problem constants
#define DIMN      1024
#define NUM_HEADS 16
#define HEAD_DIM  64
#define BATCH     2
#define SEQ       2048
#define MROWS     (BATCH * SEQ)          // 4096
#define NELEM     (MROWS * DIMN)         // 4,194,304
#define WELEM     (DIMN * DIMN)          // 1,048,576
#define QK_SCALE  0.125f

// ---------------- scratch (static device globals; no allocation) -----------
__device__ __half g_x16[3 * NELEM];   // fp16 q,k,v inputs [B,L,D]
__device__ __half g_w16[4 * WELEM];   // fp16 Wq,Wk,Wv,Wo
__device__ __half g_q16[NELEM];       // fp16 [B,H,L,hd], pre-scaled
__device__ __half g_k16[NELEM];
__device__ __half g_v16[NELEM];
__device__ __half g_a16[NELEM];       // attn output fp16 [B,L,D]

// ---------------------------------------------------------------------------
// PTX helpers
// ---------------------------------------------------------------------------
__device__ __forceinline__ uint32_t smem_cast(const void* p) {
    return (uint32_t)__cvta_generic_to_shared(p);
}
__device__ __forceinline__ void cp16(uint32_t s, const void* g) {
    asm volatile("cp.async.cg.shared.global [%0], [%1], 16;" :: "r"(s), "l"(g));
}
__device__ __forceinline__ void cp_commit() {
    asm volatile("cp.async.commit_group;");
}
template <int N>
__device__ __forceinline__ void cp_wait() {
    asm volatile("cp.async.wait_group %0;" :: "n"(N));
}
__device__ __forceinline__ void ldsm4(uint32_t& d0, uint32_t& d1, uint32_t& d2,
                                      uint32_t& d3, uint32_t a) {
    asm volatile("ldmatrix.sync.aligned.m8n8.x4.shared.b16 {%0,%1,%2,%3},[%4];"
                 : "=r"(d0), "=r"(d1), "=r"(d2), "=r"(d3) : "r"(a));
}
__device__ __forceinline__ void ldsm4t(uint32_t& d0, uint32_t& d1, uint32_t& d2,
                                       uint32_t& d3, uint32_t a) {
    asm volatile("ldmatrix.sync.aligned.m8n8.x4.trans.shared.b16 {%0,%1,%2,%3},[%4];"
                 : "=r"(d0), "=r"(d1), "=r"(d2), "=r"(d3) : "r"(a));
}
__device__ __forceinline__ void mma_f16(float* c, const uint32_t* a,
                                        uint32_t b0, uint32_t b1) {
    asm volatile(
        "mma.sync.aligned.m16n8k16.row.col.f32.f16.f16.f32 "
        "{%0,%1,%2,%3},{%4,%5,%6,%7},{%8,%9},{%0,%1,%2,%3};"
        : "+f"(c[0]), "+f"(c[1]), "+f"(c[2]), "+f"(c[3])
        : "r"(a[0]), "r"(a[1]), "r"(a[2]), "r"(a[3]), "r"(b0), "r"(b1));
}

// ---------------------------------------------------------------------------
// Convert kernel: fp32 -> fp16, up to 4 tensors selected by blockIdx.y.
// ---------------------------------------------------------------------------
__global__ __launch_bounds__(256)
void cvt_kernel(const float* __restrict__ S0, const float* __restrict__ S1,
                const float* __restrict__ S2, const float* __restrict__ S3,
                __half* __restrict__ D, int n_per)
{
    const int t = blockIdx.y;
    const float* S = (t == 0) ? S0 : (t == 1) ? S1 : (t == 2) ? S2 : S3;
    const int i = (blockIdx.x * 256 + threadIdx.x) * 4;
    if (i >= n_per) return;
    const size_t base = (size_t)t * n_per + i;
    float4 v = *(const float4*)(S + i);
    __half2 h0 = __floats2half2_rn(v.x, v.y);
    __half2 h1 = __floats2half2_rn(v.z, v.w);
    uint2 hp;
    hp.x = *(uint32_t*)&h0; hp.y = *(uint32_t*)&h1;
    *(uint2*)(D + base) = hp;
}

// ---------------------------------------------------------------------------
// fp16 tensor-core GEMM: C = A[M,K] @ W[N,K]^T + bias
// CTA tile 128x128, 256 threads, 8 warps as 4m x 2n (warp tile 32x64),
// BK=32, 3-stage cp.async (60KB smem), __launch_bounds__(256,2) -> 2 CTA/SM,
// grid (8,32) = 256 CTAs = one fully-resident wave.
// mode 0: C fp16 head-split [B,H,L,hd], scaled.  mode 1: C fp32 flat [M,N].
// ---------------------------------------------------------------------------
#define GSTR      40                        // smem row stride in fp16 (80B)
#define U_MAT_ELE (128 * GSTR)              // 5120 fp16 per 128x32 tile
#define U_STG_B   (2 * U_MAT_ELE * 2)       // A + W regions: 20480 bytes
#define U_STAGES  3
#define U_SMEM    (U_STAGES * U_STG_B)      // 61440 bytes

__global__ __launch_bounds__(256, 2)
void gemm_f16_kernel(const __half* __restrict__ A,
                     const __half* __restrict__ W,
                     const float* __restrict__ bias,
                     __half* __restrict__ Ch, float* __restrict__ Cf,
                     float scale, int mode)
{
    extern __shared__ __half sg[];
    const int tid  = threadIdx.x;
    const int lane = tid & 31;
    const int wid  = tid >> 5;
    const int wm   = wid & 3;        // 4 m-warps x 32 rows
    const int wn   = wid >> 2;       // 2 n-warps x 64 cols
    const int m0   = blockIdx.y * 128;
    const int n0   = blockIdx.x * 128;

    const uint32_t sbase = smem_cast(sg);

    float acc[2][8][4];
#pragma unroll
    for (int i = 0; i < 2; ++i)
#pragma unroll
        for (int j = 0; j < 8; ++j)
#pragma unroll
            for (int q = 0; q < 4; ++q) acc[i][j][q] = 0.0f;

    // ldmatrix offsets (bytes, within one matrix region)
    const uint32_t aoff = (uint32_t)((wm * 32 + (lane & 15)) * GSTR +
                                     (lane >> 4) * 8) * 2;
    const int bn = wn * 64 + ((lane >> 4) << 3) + (lane & 7);
    const uint32_t boff = (uint32_t)(bn * GSTR + ((lane >> 3) & 1) * 8) * 2;

    // cp.async mapping: 512 16B-chunks per matrix; idx -> row idx>>2, col (idx&3)*8
#define U_LOAD(KT, ST)                                                        \
    do {                                                                      \
        const uint32_t sb_ = sbase + (uint32_t)(ST) * U_STG_B;                \
        const int kc0 = (KT) * 32;                                            \
        _Pragma("unroll")                                                     \
        for (int i = 0; i < 2; ++i) {                                         \
            const int idx = tid + i * 256;                                    \
            const int r = idx >> 2, c = (idx & 3) << 3;                       \
            const uint32_t so = (uint32_t)(r * GSTR + c) * 2;                 \
            cp16(sb_ + so, A + (size_t)(m0 + r) * DIMN + kc0 + c);            \
            cp16(sb_ + U_MAT_ELE * 2 + so,                                    \
                 W + (size_t)(n0 + r) * DIMN + kc0 + c);                      \
        }                                                                     \
    } while (0)

    // prologue: stages 0,1
    U_LOAD(0, 0); cp_commit();
    U_LOAD(1, 1); cp_commit();

    const int NKT = DIMN / 32;   // 32
    for (int kt = 0; kt < NKT; ++kt) {
        cp_wait<1>();
        __syncthreads();
        if (kt + 2 < NKT) U_LOAD(kt + 2, (kt + 2) % 3);
        cp_commit();

        const uint32_t sb = sbase + (uint32_t)(kt % 3) * U_STG_B;
        const uint32_t aA = sb;
        const uint32_t aB = sb + U_MAT_ELE * 2;

#pragma unroll
        for (int ks = 0; ks < 2; ++ks) {
            const uint32_t ko = (uint32_t)ks * 32;   // 16 fp16 = 32 bytes
            uint32_t ah0[4], ah1[4];
            ldsm4(ah0[0], ah0[1], ah0[2], ah0[3], aA + aoff + ko);
            ldsm4(ah1[0], ah1[1], ah1[2], ah1[3],
                  aA + aoff + (uint32_t)(16 * GSTR) * 2 + ko);
#pragma unroll
            for (int p = 0; p < 4; ++p) {
                uint32_t bh[4];
                const uint32_t po = (uint32_t)(p * 16 * GSTR) * 2 + ko;
                ldsm4(bh[0], bh[1], bh[2], bh[3], aB + boff + po);
                mma_f16(acc[0][2 * p],     ah0, bh[0], bh[1]);
                mma_f16(acc[1][2 * p],     ah1, bh[0], bh[1]);
                mma_f16(acc[0][2 * p + 1], ah0, bh[2], bh[3]);
                mma_f16(acc[1][2 * p + 1], ah1, bh[2], bh[3]);
            }
        }
    }
#undef U_LOAD

    // epilogue
#pragma unroll
    for (int mt = 0; mt < 2; ++mt) {
#pragma unroll
        for (int nt = 0; nt < 8; ++nt) {
            const int rr = m0 + wm * 32 + mt * 16 + (lane >> 2);
            const int cc = n0 + wn * 64 + nt * 8 + ((lane & 3) << 1);
            const float2 bv = *(const float2*)&bias[cc];
            const float o00 = acc[mt][nt][0] + bv.x;
            const float o01 = acc[mt][nt][1] + bv.y;
            const float o10 = acc[mt][nt][2] + bv.x;
            const float o11 = acc[mt][nt][3] + bv.y;
            if (mode == 1) {
                float2 a = {o00, o01}, b = {o10, o11};
                *(float2*)&Cf[(size_t)rr * DIMN + cc]       = a;
                *(float2*)&Cf[(size_t)(rr + 8) * DIMN + cc] = b;
            } else {
                const int h = cc >> 6, hd = cc & 63;
                {
                    const int b = rr >> 11, l = rr & 2047;
                    size_t d = ((((size_t)b * NUM_HEADS + h) * SEQ + l) * HEAD_DIM + hd);
                    *(__half2*)&Ch[d] = __floats2half2_rn(o00 * scale, o01 * scale);
                }
                {
                    const int r2 = rr + 8;
                    const int b = r2 >> 11, l = r2 & 2047;
                    size_t d = ((((size_t)b * NUM_HEADS + h) * SEQ + l) * HEAD_DIM + hd);
                    *(__half2*)&Ch[d] = __floats2half2_rn(o10 * scale, o11 * scale);
                }
            }
        }
    }
}

// ---------------------------------------------------------------------------
// Tensor-core flash attention (proven): 256 threads (8 warps, 16 q/warp),
// fp16 MMA, fp32 accum, 3-stage cp.async. Output fp16 [B,L,D].
// ---------------------------------------------------------------------------
#define ASTR     72
#define A_STAGES 3

struct AttnStage {
    __half Ks[64 * ASTR];
    __half Vs[64 * ASTR];
    int    Ms[64];
};
#define A_SMEM (A_STAGES * (int)sizeof(AttnStage))

__global__ __launch_bounds__(256, 2)
void attn_mma_kernel(const __half* __restrict__ Qh, const __half* __restrict__ Kh,
                     const __half* __restrict__ Vh, const int* __restrict__ kv_mask,
                     __half* __restrict__ Out)
{
    extern __shared__ char asm_raw[];
    AttnStage* stg = (AttnStage*)asm_raw;

    const int tid  = threadIdx.x;
    const int lane = tid & 31;
    const int wid  = tid >> 5;
    const int bh   = blockIdx.y;
    const int b    = bh >> 4;
    const int h    = bh & 15;
    const int q0   = blockIdx.x * 128 + wid * 16;

    const __half* Kb = Kh + (size_t)bh * SEQ * HEAD_DIM;
    const __half* Vb = Vh + (size_t)bh * SEQ * HEAD_DIM;
    const int*    Mb = kv_mask + b * SEQ;

#define A_ISSUE(J0, ST)                                                        \
    do {                                                                       \
        uint32_t sK_ = smem_cast(stg[ST].Ks);                                  \
        uint32_t sV_ = smem_cast(stg[ST].Vs);                                  \
        uint32_t sM_ = smem_cast(stg[ST].Ms);                                  \
        for (int idx = tid; idx < 1040; idx += 256) {                          \
            if (idx < 512) {                                                   \
                int rr = idx >> 3, cc = idx & 7;                               \
                cp16(sK_ + (uint32_t)(rr * ASTR + cc * 8) * 2,                 \
                     Kb + (size_t)((J0) + rr) * HEAD_DIM + cc * 8);            \
            } else if (idx < 1024) {                                           \
                int q = idx - 512, rr = q >> 3, cc = q & 7;                    \
                cp16(sV_ + (uint32_t)(rr * ASTR + cc * 8) * 2,                 \
                     Vb + (size_t)((J0) + rr) * HEAD_DIM + cc * 8);            \
            } else {                                                           \
                int q = idx - 1024;                                            \
                cp16(sM_ + (uint32_t)q * 16, Mb + (J0) + q * 4);               \
            }                                                                  \
        }                                                                      \
    } while (0)

    A_ISSUE(0, 0);  cp_commit();
    A_ISSUE(64, 1); cp_commit();

    uint32_t aq[4][4];
    {
        const __half* Qb = Qh + (size_t)bh * SEQ * HEAD_DIM;
#pragma unroll
        for (int ks = 0; ks < 4; ++ks)
#pragma unroll
            for (int j = 0; j < 4; ++j) {
                const int rr = q0 + (lane >> 2) + (j & 1) * 8;
                const int cc = ks * 16 + ((j >> 1) << 3) + ((lane & 3) << 1);
                aq[ks][j] = *(const uint32_t*)&Qb[(size_t)rr * HEAD_DIM + cc];
            }
    }

    float O[8][4];
#pragma unroll
    for (int i = 0; i < 8; ++i)
#pragma unroll
        for (int j = 0; j < 4; ++j) O[i][j] = 0.0f;
    float m0r = -1e30f, m1r = -1e30f, l0r = 0.0f, l1r = 0.0f;

    const uint32_t kfrag =
        (uint32_t)(((((lane >> 4) << 3) + (lane & 7)) * ASTR + ((lane >> 3) & 1) * 8)) * 2;
    const uint32_t vfrag =
        (uint32_t)((((((lane >> 3) & 1) << 3) + (lane & 7)) * ASTR + (lane >> 4) * 8)) * 2;

    const int NT = SEQ / 64;
    for (int kt = 0; kt < NT; ++kt) {
        cp_wait<1>();
        __syncthreads();
        if (kt + 2 < NT) A_ISSUE((kt + 2) * 64, (kt + 2) % A_STAGES);
        cp_commit();

        AttnStage* st = &stg[kt % A_STAGES];
        const uint32_t aK = smem_cast(st->Ks);
        const uint32_t aV = smem_cast(st->Vs);

        float S[8][4];
#pragma unroll
        for (int i = 0; i < 8; ++i)
#pragma unroll
            for (int j = 0; j < 4; ++j) S[i][j] = 0.0f;
#pragma unroll
        for (int ks = 0; ks < 4; ++ks) {
#pragma unroll
            for (int p = 0; p < 4; ++p) {
                uint32_t bq[4];
                ldsm4(bq[0], bq[1], bq[2], bq[3],
                      aK + kfrag + (uint32_t)(p * 16 * ASTR * 2 + ks * 32));
                mma_f16(S[2 * p],     aq[ks], bq[0], bq[1]);
                mma_f16(S[2 * p + 1], aq[ks], bq[2], bq[3]);
            }
        }

        float mx0 = -1e30f, mx1 = -1e30f;
#pragma unroll
        for (int nt = 0; nt < 8; ++nt) {
            const int kk = nt * 8 + ((lane & 3) << 1);
            const int2 mi = *(const int2*)&st->Ms[kk];
            const float mdx = mi.x ? 0.0f : -1e30f;
            const float mdy = mi.y ? 0.0f : -1e30f;
            S[nt][0] += mdx; S[nt][1] += mdy;
            S[nt][2] += mdx; S[nt][3] += mdy;
            mx0 = fmaxf(mx0, fmaxf(S[nt][0], S[nt][1]));
            mx1 = fmaxf(mx1, fmaxf(S[nt][2], S[nt][3]));
        }
        mx0 = fmaxf(mx0, __shfl_xor_sync(0xffffffffu, mx0, 1));
        mx0 = fmaxf(mx0, __shfl_xor_sync(0xffffffffu, mx0, 2));
        mx1 = fmaxf(mx1, __shfl_xor_sync(0xffffffffu, mx1, 1));
        mx1 = fmaxf(mx1, __shfl_xor_sync(0xffffffffu, mx1, 2));

        const float nm0 = fmaxf(m0r, mx0), nm1 = fmaxf(m1r, mx1);
        const float f0 = __expf(m0r - nm0), f1 = __expf(m1r - nm1);
        m0r = nm0; m1r = nm1;

        float s0 = 0.0f, s1 = 0.0f;
#pragma unroll
        for (int nt = 0; nt < 8; ++nt) {
            S[nt][0] = __expf(S[nt][0] - nm0);
            S[nt][1] = __expf(S[nt][1] - nm0);
            S[nt][2] = __expf(S[nt][2] - nm1);
            S[nt][3] = __expf(S[nt][3] - nm1);
            s0 += S[nt][0] + S[nt][1];
            s1 += S[nt][2] + S[nt][3];
        }
        s0 += __shfl_xor_sync(0xffffffffu, s0, 1);
        s0 += __shfl_xor_sync(0xffffffffu, s0, 2);
        s1 += __shfl_xor_sync(0xffffffffu, s1, 1);
        s1 += __shfl_xor_sync(0xffffffffu, s1, 2);
        l0r = l0r * f0 + s0;
        l1r = l1r * f1 + s1;

#pragma unroll
        for (int nt = 0; nt < 8; ++nt) {
            O[nt][0] *= f0; O[nt][1] *= f0;
            O[nt][2] *= f1; O[nt][3] *= f1;
        }

#pragma unroll
        for (int ks = 0; ks < 4; ++ks) {
            uint32_t pa[4];
            {
                __half2 t0 = __floats2half2_rn(S[2 * ks][0],     S[2 * ks][1]);
                __half2 t1 = __floats2half2_rn(S[2 * ks][2],     S[2 * ks][3]);
                __half2 t2 = __floats2half2_rn(S[2 * ks + 1][0], S[2 * ks + 1][1]);
                __half2 t3 = __floats2half2_rn(S[2 * ks + 1][2], S[2 * ks + 1][3]);
                pa[0] = *(uint32_t*)&t0; pa[1] = *(uint32_t*)&t1;
                pa[2] = *(uint32_t*)&t2; pa[3] = *(uint32_t*)&t3;
            }
#pragma unroll
            for (int p = 0; p < 4; ++p) {
                uint32_t bv[4];
                ldsm4t(bv[0], bv[1], bv[2], bv[3],
                       aV + vfrag + (uint32_t)(ks * 16 * ASTR * 2 + p * 32));
                mma_f16(O[2 * p],     pa, bv[0], bv[1]);
                mma_f16(O[2 * p + 1], pa, bv[2], bv[3]);
            }
        }
    }
#undef A_ISSUE

    const float inv0 = 1.0f / l0r, inv1 = 1.0f / l1r;
    const int qr = q0 + (lane >> 2);
    const size_t base0 = ((size_t)b * SEQ + qr) * DIMN + h * HEAD_DIM;
    const size_t base1 = ((size_t)b * SEQ + qr + 8) * DIMN + h * HEAD_DIM;
#pragma unroll
    for (int nt = 0; nt < 8; ++nt) {
        const int c = nt * 8 + ((lane & 3) << 1);
        *(__half2*)&Out[base0 + c] = __floats2half2_rn(O[nt][0] * inv0, O[nt][1] * inv0);
        *(__half2*)&Out[base1 + c] = __floats2half2_rn(O[nt][2] * inv1, O[nt][3] * inv1);
    }
}

// ---------------------------------------------------------------------------
extern "C" void kernel_launch(void* const* d_in, const int* in_sizes, int n_in,
                              void* d_out, int out_size)
{
    const float* q    = (const float*)d_in[0];
    const float* k    = (const float*)d_in[1];
    const float* v    = (const float*)d_in[2];
    const int*   mask = (const int*)  d_in[3];
    const float* Wq   = (const float*)d_in[4];
    const float* bq   = (const float*)d_in[5];
    const float* Wk   = (const float*)d_in[6];
    const float* bk   = (const float*)d_in[7];
    const float* Wv   = (const float*)d_in[8];
    const float* bv   = (const float*)d_in[9];
    const float* Wo   = (const float*)d_in[10];
    const float* bo   = (const float*)d_in[11];
    float*       out  = (float*)d_out;

    static bool attr_done = false;
    if (!attr_done) {
        cudaFuncSetAttribute(gemm_f16_kernel,
                             cudaFuncAttributeMaxDynamicSharedMemorySize, U_SMEM);
        cudaFuncSetAttribute(attn_mma_kernel,
                             cudaFuncAttributeMaxDynamicSharedMemorySize, A_SMEM);
        attr_done = true;
    }

    void *p_x16, *p_w16, *p_q16, *p_k16, *p_v16, *p_a16;
    cudaGetSymbolAddress(&p_x16, g_x16);
    cudaGetSymbolAddress(&p_w16, g_w16);
    cudaGetSymbolAddress(&p_q16, g_q16);
    cudaGetSymbolAddress(&p_k16, g_k16);
    cudaGetSymbolAddress(&p_v16, g_v16);
    cudaGetSymbolAddress(&p_a16, g_a16);

    __half* x16 = (__half*)p_x16;
    __half* w16 = (__half*)p_w16;

    // convert inputs (3 x 4M) and weights (4 x 1M) to fp16
    cvt_kernel<<<dim3(NELEM / 1024, 3), 256>>>(q, k, v, nullptr, x16, NELEM);
    cvt_kernel<<<dim3(WELEM / 1024, 4), 256>>>(Wq, Wk, Wv, Wo, w16, WELEM);

    dim3 gg(DIMN / 128, MROWS / 128);   // (8, 32) = 256 CTAs, 2/SM, one wave
    gemm_f16_kernel<<<gg, 256, U_SMEM>>>(x16, w16, bq,
                                         (__half*)p_q16, nullptr, QK_SCALE, 0);
    gemm_f16_kernel<<<gg, 256, U_SMEM>>>(x16 + (size_t)NELEM,
                                         w16 + (size_t)WELEM, bk,
                                         (__half*)p_k16, nullptr, 1.0f, 0);
    gemm_f16_kernel<<<gg, 256, U_SMEM>>>(x16 + 2 * (size_t)NELEM,
                                         w16 + 2 * (size_t)WELEM, bv,
                                         (__half*)p_v16, nullptr, 1.0f, 0);

    dim3 ag(SEQ / 128, BATCH * NUM_HEADS);   // (16, 32)
    attn_mma_kernel<<<ag, 256, A_SMEM>>>((const __half*)p_q16, (const __half*)p_k16,
                                         (const __half*)p_v16, mask,
                                         (__half*)p_a16);

    gemm_f16_kernel<<<gg, 256, U_SMEM>>>((const __half*)p_a16,
                                         w16 + 3 * (size_t)WELEM, bo,
                                         nullptr, out, 1.0f, 1);
}